// round 5
// baseline (speedup 1.0000x reference)
#include <cuda_runtime.h>
#include <cuda_fp16.h>
#include <cuda_bf16.h>

#define NN 50000
#define NE 1600000
#define INF 128
#define UNITS 64
#define OUTF 40
#define NL 6
#define HCATW (NL * UNITS)   // 384

// ---- device-global scratch (no allocation allowed) ----
__device__ __half g_ylin_h[NN * UNITS];     // h @ w_lin in fp16 (gather source)
__device__ float  g_hpre[NN * UNITS];       // h @ w_self + (bl+bs+bias), fp32
__device__ float  g_hcat[NN * HCATW];       // relu'd layer outputs (also next-layer input)
__device__ int    g_deg[NN];
__device__ int    g_rowptr[NN + 1];
__device__ int    g_cursor[NN];
__device__ int    g_csr_src[NE];

// ============================================================================
// CSR build (4 edges per thread for MLP)
// ============================================================================
__global__ void zero_deg()
{
    int i = blockIdx.x * 256 + threadIdx.x;
    if (i < NN) g_deg[i] = 0;
}

__global__ void hist_deg4(const int* __restrict__ dst)
{
    int i = blockIdx.x * 256 + threadIdx.x;
    if (i >= NE / 4) return;
    int4 d = ((const int4*)dst)[i];
    atomicAdd(&g_deg[d.x], 1);
    atomicAdd(&g_deg[d.y], 1);
    atomicAdd(&g_deg[d.z], 1);
    atomicAdd(&g_deg[d.w], 1);
}

__global__ void scan_csr()   // 1 block, 1024 threads
{
    __shared__ int sums[1024];
    const int CH = (NN + 1023) / 1024;   // 49
    const int t = threadIdx.x;
    const int base = t * CH;
    int s = 0;
    for (int i = 0; i < CH; i++) {
        int idx = base + i;
        if (idx < NN) s += g_deg[idx];
    }
    sums[t] = s;
    __syncthreads();
    for (int off = 1; off < 1024; off <<= 1) {
        int v = (t >= off) ? sums[t - off] : 0;
        __syncthreads();
        sums[t] += v;
        __syncthreads();
    }
    int run = sums[t] - s;
    for (int i = 0; i < CH; i++) {
        int idx = base + i;
        if (idx < NN) {
            g_rowptr[idx] = run;
            g_cursor[idx] = run;
            run += g_deg[idx];
        }
    }
    if (t == 1023) g_rowptr[NN] = sums[1023];
}

__global__ void fill_csr4(const int* __restrict__ src, const int* __restrict__ dst)
{
    int i = blockIdx.x * 256 + threadIdx.x;
    if (i >= NE / 4) return;
    int4 s = ((const int4*)src)[i];
    int4 d = ((const int4*)dst)[i];
    int p0 = atomicAdd(&g_cursor[d.x], 1);
    int p1 = atomicAdd(&g_cursor[d.y], 1);
    int p2 = atomicAdd(&g_cursor[d.z], 1);
    int p3 = atomicAdd(&g_cursor[d.w], 1);
    g_csr_src[p0] = s.x;
    g_csr_src[p1] = s.y;
    g_csr_src[p2] = s.z;
    g_csr_src[p3] = s.w;
}

// ============================================================================
// Dual GEMM, 4x4 register tile, transposed h in smem ([k][row]) so the 4-row
// operand is a single LDS.128:
//   g_ylin_h = fp16(in @ wl) ;  g_hpre = in @ ws + (bl + bs + bias)
// ============================================================================
template <int K>
__global__ void gemm_dual(const float* __restrict__ in, int in_stride,
                          const float* __restrict__ wl, const float* __restrict__ ws,
                          const float* __restrict__ bl, const float* __restrict__ bs,
                          const float* __restrict__ bias)
{
    extern __shared__ float sm[];
    float* sh_wl = sm;                 // [K][64]
    float* sh_ws = sm + K * 64;        // [K][64]
    float* sh_h  = sm + 2 * K * 64;    // [K][64]  transposed: sh_h[k*64 + r]

    const int tid = threadIdx.x;
    for (int i = tid; i < K * 16; i += 256) {
        ((float4*)sh_wl)[i] = ((const float4*)wl)[i];
        ((float4*)sh_ws)[i] = ((const float4*)ws)[i];
    }
    const int row0 = blockIdx.x * 64;
    for (int i = tid; i < 64 * (K / 4); i += 256) {
        int r = i / (K / 4), kq = i % (K / 4);
        int gr = row0 + r;
        float4 v = make_float4(0.f, 0.f, 0.f, 0.f);
        if (gr < NN) v = ((const float4*)(in + (size_t)gr * in_stride))[kq];
        sh_h[(kq * 4 + 0) * 64 + r] = v.x;
        sh_h[(kq * 4 + 1) * 64 + r] = v.y;
        sh_h[(kq * 4 + 2) * 64 + r] = v.z;
        sh_h[(kq * 4 + 3) * 64 + r] = v.w;
    }
    __syncthreads();

    const int tx = tid & 15, ty = tid >> 4;
    const int c0 = tx * 4, r0 = ty * 4;

    float accl[4][4] = {}, accs[4][4] = {};
#pragma unroll 8
    for (int k = 0; k < K; k++) {
        const float4 wlv = ((const float4*)(sh_wl + k * 64))[tx];
        const float4 wsv = ((const float4*)(sh_ws + k * 64))[tx];
        const float4 h4  = *(const float4*)(sh_h + k * 64 + r0);
        const float h[4] = { h4.x, h4.y, h4.z, h4.w };
#pragma unroll
        for (int j = 0; j < 4; j++) {
            accl[j][0] += h[j] * wlv.x; accl[j][1] += h[j] * wlv.y;
            accl[j][2] += h[j] * wlv.z; accl[j][3] += h[j] * wlv.w;
            accs[j][0] += h[j] * wsv.x; accs[j][1] += h[j] * wsv.y;
            accs[j][2] += h[j] * wsv.z; accs[j][3] += h[j] * wsv.w;
        }
    }

    float4 bt;
    bt.x = bl[c0+0] + bs[c0+0] + bias[c0+0];
    bt.y = bl[c0+1] + bs[c0+1] + bias[c0+1];
    bt.z = bl[c0+2] + bs[c0+2] + bias[c0+2];
    bt.w = bl[c0+3] + bs[c0+3] + bias[c0+3];

#pragma unroll
    for (int j = 0; j < 4; j++) {
        int gr = row0 + r0 + j;
        if (gr < NN) {
            __half2 p0 = __floats2half2_rn(accl[j][0], accl[j][1]);
            __half2 p1 = __floats2half2_rn(accl[j][2], accl[j][3]);
            uint2 u = make_uint2(*(unsigned*)&p0, *(unsigned*)&p1);
            ((uint2*)(g_ylin_h + gr * 64))[tx] = u;
            float4 hp = make_float4(accs[j][0] + bt.x, accs[j][1] + bt.y,
                                    accs[j][2] + bt.z, accs[j][3] + bt.w);
            ((float4*)(g_hpre + gr * 64))[tx] = hp;
        }
    }
}

// ============================================================================
// Gather aggregation + relu + store into hcat slice.
// 8 threads per node, each owns 8 halves (one uint4). Edge loop unrolled x8.
// ============================================================================
__device__ __forceinline__ void acc8(float* acc, uint4 u)
{
    float2 f;
    f = __half22float2(*(__half2*)&u.x); acc[0] += f.x; acc[1] += f.y;
    f = __half22float2(*(__half2*)&u.y); acc[2] += f.x; acc[3] += f.y;
    f = __half22float2(*(__half2*)&u.z); acc[4] += f.x; acc[5] += f.y;
    f = __half22float2(*(__half2*)&u.w); acc[6] += f.x; acc[7] += f.y;
}

__global__ void __launch_bounds__(256) gather_relu(int layer)
{
    const int t = blockIdx.x * 256 + threadIdx.x;
    const int v = t >> 3;
    const int q = t & 7;
    if (v >= NN) return;
    const int beg = g_rowptr[v];
    const int end = g_rowptr[v + 1];

    const uint4* base = (const uint4*)g_ylin_h;   // 8 uint4 per node row
    float acc[8] = {};

    int e = beg;
    for (; e + 8 <= end; e += 8) {
        int s0 = g_csr_src[e + 0];
        int s1 = g_csr_src[e + 1];
        int s2 = g_csr_src[e + 2];
        int s3 = g_csr_src[e + 3];
        int s4 = g_csr_src[e + 4];
        int s5 = g_csr_src[e + 5];
        int s6 = g_csr_src[e + 6];
        int s7 = g_csr_src[e + 7];
        uint4 a = base[s0 * 8 + q];
        uint4 b = base[s1 * 8 + q];
        uint4 c = base[s2 * 8 + q];
        uint4 d = base[s3 * 8 + q];
        uint4 a2 = base[s4 * 8 + q];
        uint4 b2 = base[s5 * 8 + q];
        uint4 c2 = base[s6 * 8 + q];
        uint4 d2 = base[s7 * 8 + q];
        acc8(acc, a);  acc8(acc, b);  acc8(acc, c);  acc8(acc, d);
        acc8(acc, a2); acc8(acc, b2); acc8(acc, c2); acc8(acc, d2);
    }
    for (; e + 4 <= end; e += 4) {
        int s0 = g_csr_src[e + 0];
        int s1 = g_csr_src[e + 1];
        int s2 = g_csr_src[e + 2];
        int s3 = g_csr_src[e + 3];
        uint4 a = base[s0 * 8 + q];
        uint4 b = base[s1 * 8 + q];
        uint4 c = base[s2 * 8 + q];
        uint4 d = base[s3 * 8 + q];
        acc8(acc, a); acc8(acc, b); acc8(acc, c); acc8(acc, d);
    }
    for (; e < end; e++) {
        int s = g_csr_src[e];
        acc8(acc, base[s * 8 + q]);
    }

    const float4 hp0 = *(const float4*)(g_hpre + v * 64 + q * 8);
    const float4 hp1 = *(const float4*)(g_hpre + v * 64 + q * 8 + 4);
    float* outp = g_hcat + (size_t)v * HCATW + layer * UNITS + q * 8;
    float4 o0, o1;
    o0.x = fmaxf(hp0.x + acc[0], 0.f);
    o0.y = fmaxf(hp0.y + acc[1], 0.f);
    o0.z = fmaxf(hp0.z + acc[2], 0.f);
    o0.w = fmaxf(hp0.w + acc[3], 0.f);
    o1.x = fmaxf(hp1.x + acc[4], 0.f);
    o1.y = fmaxf(hp1.y + acc[5], 0.f);
    o1.z = fmaxf(hp1.z + acc[6], 0.f);
    o1.w = fmaxf(hp1.w + acc[7], 0.f);
    *(float4*)(outp)     = o0;
    *(float4*)(outp + 4) = o1;
}

// ============================================================================
// Final: out = hcat @ w_last + b_last   [NN,384] @ [384,40]
// ============================================================================
__global__ void gemm_last(const float* __restrict__ w, const float* __restrict__ b,
                          float* __restrict__ out)
{
    extern __shared__ float sm[];
    float* sh_w = sm;                  // [384][40]
    float* sh_h = sm + HCATW * OUTF;   // [64][64]

    const int tid = threadIdx.x;       // 0..159
    for (int i = tid; i < HCATW * OUTF / 4; i += 160)
        ((float4*)sh_w)[i] = ((const float4*)w)[i];

    const int row0 = blockIdx.x * 64;
    const int tx = tid % 10, ty = tid / 10;
    const int c0 = tx * 4, r0 = ty * 4;
    float acc[4][4] = {};

    for (int kt = 0; kt < HCATW / 64; kt++) {
        __syncthreads();
        for (int i = tid; i < 64 * 16; i += 160) {
            int r = i / 16, kq = i % 16;
            int gr = row0 + r;
            float4 v = make_float4(0.f, 0.f, 0.f, 0.f);
            if (gr < NN) v = *(const float4*)(g_hcat + (size_t)gr * HCATW + kt * 64 + kq * 4);
            ((float4*)(sh_h + r * 64))[kq] = v;
        }
        __syncthreads();
#pragma unroll 8
        for (int kk = 0; kk < 64; kk++) {
            const int k = kt * 64 + kk;
            const float4 wv = ((const float4*)(sh_w + k * OUTF))[tx];
            float h[4];
#pragma unroll
            for (int j = 0; j < 4; j++) h[j] = sh_h[(r0 + j) * 64 + kk];
#pragma unroll
            for (int j = 0; j < 4; j++) {
                acc[j][0] += h[j] * wv.x; acc[j][1] += h[j] * wv.y;
                acc[j][2] += h[j] * wv.z; acc[j][3] += h[j] * wv.w;
            }
        }
    }

    float4 bv = *(const float4*)(b + c0);
#pragma unroll
    for (int j = 0; j < 4; j++) {
        int gr = row0 + r0 + j;
        if (gr < NN) {
            float4 o = make_float4(acc[j][0] + bv.x, acc[j][1] + bv.y,
                                   acc[j][2] + bv.z, acc[j][3] + bv.w);
            *(float4*)(out + (size_t)gr * OUTF + c0) = o;
        }
    }
}

// ============================================================================
extern "C" void kernel_launch(void* const* d_in, const int* in_sizes, int n_in,
                              void* d_out, int out_size)
{
    const float* x      = (const float*)d_in[0];
    const int*   src    = (const int*)  d_in[1];
    const int*   dst    = (const int*)  d_in[2];
    const float* w0l    = (const float*)d_in[3];
    const float* b0l    = (const float*)d_in[4];
    const float* w0s    = (const float*)d_in[5];
    const float* b0s    = (const float*)d_in[6];
    const float* bias0  = (const float*)d_in[7];
    const float* w_lin  = (const float*)d_in[8];
    const float* b_lin  = (const float*)d_in[9];
    const float* w_self = (const float*)d_in[10];
    const float* b_self = (const float*)d_in[11];
    const float* bias   = (const float*)d_in[12];
    const float* w_last = (const float*)d_in[13];
    const float* b_last = (const float*)d_in[14];
    float* out = (float*)d_out;

    const int SMEM0 = (3 * INF * 64) * 4;                       // 98304
    const int SMEM1 = (3 * 64 * 64) * 4;                        // 49152
    const int SMEML = (HCATW * OUTF + 64 * 64) * 4;             // 77824

    cudaFuncSetAttribute((const void*)gemm_dual<INF>,
                         cudaFuncAttributeMaxDynamicSharedMemorySize, SMEM0);
    cudaFuncSetAttribute((const void*)gemm_dual<64>,
                         cudaFuncAttributeMaxDynamicSharedMemorySize, SMEM1);
    cudaFuncSetAttribute((const void*)gemm_last,
                         cudaFuncAttributeMaxDynamicSharedMemorySize, SMEML);

    void* hcat_p = nullptr;
    cudaGetSymbolAddress(&hcat_p, g_hcat);
    const float* hcat = (const float*)hcat_p;

    const int nblk     = (NN + 63) / 64;            // 782
    const int e4blk    = (NE / 4 + 255) / 256;      // 1563
    const int nodeblk  = (NN + 255) / 256;          // 196
    const int gathblk  = (NN * 8 + 255) / 256;      // 1563

    // ---- CSR build (once per launch) ----
    zero_deg<<<nodeblk, 256>>>();
    hist_deg4<<<e4blk, 256>>>(dst);
    scan_csr<<<1, 1024>>>();
    fill_csr4<<<e4blk, 256>>>(src, dst);

    // ---- Layer 0 (input x, K=128) ----
    gemm_dual<INF><<<nblk, 256, SMEM0>>>(x, INF, w0l, w0s, b0l, b0s, bias0);
    gather_relu<<<gathblk, 256>>>(0);

    // ---- Layers 1..5 ----
    for (int l = 1; l < NL; l++) {
        const float* in = hcat + (l - 1) * UNITS;
        const float* wl = w_lin  + (l - 1) * 64 * 64;
        const float* bl = b_lin  + (l - 1) * 64;
        const float* ws = w_self + (l - 1) * 64 * 64;
        const float* bs = b_self + (l - 1) * 64;
        const float* bi = bias   + (l - 1) * 64;
        gemm_dual<64><<<nblk, 256, SMEM1>>>(in, HCATW, wl, ws, bl, bs, bi);
        gather_relu<<<gathblk, 256>>>(l);
    }

    // ---- Final projection ----
    gemm_last<<<nblk, 160, SMEML>>>(w_last, b_last, out);
}

// round 9
// speedup vs baseline: 1.0206x; 1.0206x over previous
#include <cuda_runtime.h>
#include <cuda_fp16.h>
#include <cuda_bf16.h>

#define NN 50000
#define NE 1600000
#define INF 128
#define UNITS 64
#define OUTF 40
#define NL 6
#define HCATW (NL * UNITS)   // 384

// ---- device-global scratch (no allocation allowed) ----
// Ping-pong buffers: fused layers read [cur], write [cur^1]. This prevents the
// inter-block race of in-place update (gather reads arbitrary rows).
__device__ __half g_ylin_h[2][NN * UNITS];
__device__ float  g_hpre[2][NN * UNITS];
__device__ float  g_hcat[NN * HCATW];       // relu'd layer outputs (concat buffer)
__device__ int    g_deg[NN];
__device__ int    g_rowptr[NN + 1];
__device__ int    g_cursor[NN];
__device__ int    g_csr_src[NE];

// ============================================================================
// CSR build
// ============================================================================
__global__ void zero_deg()
{
    int i = blockIdx.x * 256 + threadIdx.x;
    if (i < NN) g_deg[i] = 0;
}

__global__ void hist_deg(const int* __restrict__ dst)
{
    int e = blockIdx.x * 256 + threadIdx.x;
    if (e < NE) atomicAdd(&g_deg[dst[e]], 1);
}

__global__ void scan_csr()   // 1 block, 1024 threads
{
    __shared__ int sums[1024];
    const int CH = (NN + 1023) / 1024;   // 49
    const int t = threadIdx.x;
    const int base = t * CH;
    int s = 0;
    for (int i = 0; i < CH; i++) {
        int idx = base + i;
        if (idx < NN) s += g_deg[idx];
    }
    sums[t] = s;
    __syncthreads();
    for (int off = 1; off < 1024; off <<= 1) {
        int v = (t >= off) ? sums[t - off] : 0;
        __syncthreads();
        sums[t] += v;
        __syncthreads();
    }
    int run = sums[t] - s;
    for (int i = 0; i < CH; i++) {
        int idx = base + i;
        if (idx < NN) {
            g_rowptr[idx] = run;
            g_cursor[idx] = run;
            run += g_deg[idx];
        }
    }
    if (t == 1023) g_rowptr[NN] = sums[1023];
}

__global__ void fill_csr(const int* __restrict__ src, const int* __restrict__ dst)
{
    int e = blockIdx.x * 256 + threadIdx.x;
    if (e >= NE) return;
    int pos = atomicAdd(&g_cursor[dst[e]], 1);
    g_csr_src[pos] = src[e];
}

// ============================================================================
// Gather helper: fp16 row accumulate
// ============================================================================
__device__ __forceinline__ void acc8(float* acc, uint4 u)
{
    float2 f;
    f = __half22float2(*(__half2*)&u.x); acc[0] += f.x; acc[1] += f.y;
    f = __half22float2(*(__half2*)&u.y); acc[2] += f.x; acc[3] += f.y;
    f = __half22float2(*(__half2*)&u.z); acc[4] += f.x; acc[5] += f.y;
    f = __half22float2(*(__half2*)&u.w); acc[6] += f.x; acc[7] += f.y;
}

// Gather one node's q-chunk (8 halves) from the given ylin buffer.
__device__ __forceinline__ void gather_node(const __half* ylin, int v, int q, float* acc)
{
    const int beg = g_rowptr[v];
    const int end = g_rowptr[v + 1];
    const uint4* base = (const uint4*)ylin;   // 8 uint4 per node row
    int e = beg;
    for (; e + 4 <= end; e += 4) {
        int s0 = g_csr_src[e + 0];
        int s1 = g_csr_src[e + 1];
        int s2 = g_csr_src[e + 2];
        int s3 = g_csr_src[e + 3];
        uint4 a = base[s0 * 8 + q];
        uint4 b = base[s1 * 8 + q];
        uint4 c = base[s2 * 8 + q];
        uint4 d = base[s3 * 8 + q];
        acc8(acc, a); acc8(acc, b); acc8(acc, c); acc8(acc, d);
    }
    for (; e < end; e++) {
        int s = g_csr_src[e];
        acc8(acc, base[s * 8 + q]);
    }
}

// ============================================================================
// Layer-0 dual GEMM from x -> buffers [0]:
//   g_ylin_h[0] = fp16(in @ wl) ;  g_hpre[0] = in @ ws + (bl + bs + bias)
// ============================================================================
template <int K>
__global__ void gemm_dual(const float* __restrict__ in, int in_stride,
                          const float* __restrict__ wl, const float* __restrict__ ws,
                          const float* __restrict__ bl, const float* __restrict__ bs,
                          const float* __restrict__ bias)
{
    extern __shared__ float sm[];
    float* sh_wl = sm;                 // [K][64]
    float* sh_ws = sm + K * 64;        // [K][64]
    float* sh_h  = sm + 2 * K * 64;    // [64][K]

    const int tid = threadIdx.x;
    for (int i = tid; i < K * 16; i += 256) {
        ((float4*)sh_wl)[i] = ((const float4*)wl)[i];
        ((float4*)sh_ws)[i] = ((const float4*)ws)[i];
    }
    const int row0 = blockIdx.x * 64;
    for (int i = tid; i < 64 * (K / 4); i += 256) {
        int r = i / (K / 4), kq = i % (K / 4);
        int gr = row0 + r;
        float4 v = make_float4(0.f, 0.f, 0.f, 0.f);
        if (gr < NN) v = ((const float4*)(in + (size_t)gr * in_stride))[kq];
        ((float4*)(sh_h + r * K))[kq] = v;
    }
    __syncthreads();

    const int tx = tid & 15, ty = tid >> 4;
    const int c0 = tx * 4, r0 = ty * 4;

    float accl[4][4] = {}, accs[4][4] = {};
#pragma unroll 8
    for (int k = 0; k < K; k++) {
        const float4 wlv = ((const float4*)(sh_wl + k * 64))[tx];
        const float4 wsv = ((const float4*)(sh_ws + k * 64))[tx];
        float h[4];
#pragma unroll
        for (int j = 0; j < 4; j++) h[j] = sh_h[(r0 + j) * K + k];
#pragma unroll
        for (int j = 0; j < 4; j++) {
            accl[j][0] += h[j] * wlv.x; accl[j][1] += h[j] * wlv.y;
            accl[j][2] += h[j] * wlv.z; accl[j][3] += h[j] * wlv.w;
            accs[j][0] += h[j] * wsv.x; accs[j][1] += h[j] * wsv.y;
            accs[j][2] += h[j] * wsv.z; accs[j][3] += h[j] * wsv.w;
        }
    }

    float4 bt;
    bt.x = bl[c0+0] + bs[c0+0] + bias[c0+0];
    bt.y = bl[c0+1] + bs[c0+1] + bias[c0+1];
    bt.z = bl[c0+2] + bs[c0+2] + bias[c0+2];
    bt.w = bl[c0+3] + bs[c0+3] + bias[c0+3];

#pragma unroll
    for (int j = 0; j < 4; j++) {
        int gr = row0 + r0 + j;
        if (gr < NN) {
            __half2 p0 = __floats2half2_rn(accl[j][0], accl[j][1]);
            __half2 p1 = __floats2half2_rn(accl[j][2], accl[j][3]);
            uint2 u = make_uint2(*(unsigned*)&p0, *(unsigned*)&p1);
            ((uint2*)(g_ylin_h[0] + gr * 64))[tx] = u;
            float4 hp = make_float4(accs[j][0] + bt.x, accs[j][1] + bt.y,
                                    accs[j][2] + bt.z, accs[j][3] + bt.w);
            ((float4*)(g_hpre[0] + gr * 64))[tx] = hp;
        }
    }
}

// ============================================================================
// Fused per-layer kernel with ping-pong:
//   Phase 1: gather+relu block's 64 rows from buffers [cur] into smem
//            (and write the hcat slice `slice`).
//   Phase 2: dual GEMM h @ wl / h @ ws -> buffers [cur^1].
// ============================================================================
__global__ void __launch_bounds__(256) fused_gather_gemm(
    int slice, int cur,
    const float* __restrict__ wl, const float* __restrict__ ws,
    const float* __restrict__ bl, const float* __restrict__ bs,
    const float* __restrict__ bias)
{
    extern __shared__ float sm[];
    float* sh_wl = sm;                 // [64][64]
    float* sh_ws = sm + 4096;          // [64][64]
    float* sh_h  = sm + 8192;          // [64][64] row-major

    const int tid = threadIdx.x;
    const int row0 = blockIdx.x * 64;
    const __half* ylin_src = g_ylin_h[cur];
    const float*  hpre_src = g_hpre[cur];
    __half* ylin_dst = g_ylin_h[cur ^ 1];
    float*  hpre_dst = g_hpre[cur ^ 1];

    // weight loads issue first (independent of gather)
    for (int i = tid; i < 1024; i += 256) {
        ((float4*)sh_wl)[i] = ((const float4*)wl)[i];
        ((float4*)sh_ws)[i] = ((const float4*)ws)[i];
    }

    // ---- Phase 1: gather + relu (8 threads per row, 2 rows per thread) ----
    {
        const int q  = tid & 7;        // 8-half chunk
        const int rl = tid >> 3;       // 0..31
#pragma unroll
        for (int rr = 0; rr < 64; rr += 32) {
            const int r = rl + rr;
            const int v = row0 + r;
            float4 o0 = make_float4(0.f, 0.f, 0.f, 0.f);
            float4 o1 = make_float4(0.f, 0.f, 0.f, 0.f);
            if (v < NN) {
                float acc[8] = {};
                gather_node(ylin_src, v, q, acc);
                const float4 hp0 = *(const float4*)(hpre_src + v * 64 + q * 8);
                const float4 hp1 = *(const float4*)(hpre_src + v * 64 + q * 8 + 4);
                o0.x = fmaxf(hp0.x + acc[0], 0.f);
                o0.y = fmaxf(hp0.y + acc[1], 0.f);
                o0.z = fmaxf(hp0.z + acc[2], 0.f);
                o0.w = fmaxf(hp0.w + acc[3], 0.f);
                o1.x = fmaxf(hp1.x + acc[4], 0.f);
                o1.y = fmaxf(hp1.y + acc[5], 0.f);
                o1.z = fmaxf(hp1.z + acc[6], 0.f);
                o1.w = fmaxf(hp1.w + acc[7], 0.f);
                float* outp = g_hcat + (size_t)v * HCATW + slice * UNITS + q * 8;
                *(float4*)(outp)     = o0;
                *(float4*)(outp + 4) = o1;
            }
            *(float4*)(sh_h + r * 64 + q * 8)     = o0;
            *(float4*)(sh_h + r * 64 + q * 8 + 4) = o1;
        }
    }
    __syncthreads();

    // ---- Phase 2: dual GEMM out of smem -> buffers [cur^1] ----
    const int tx = tid & 15, ty = tid >> 4;
    const int c0 = tx * 4, r0 = ty * 4;

    float accl[4][4] = {}, accs[4][4] = {};
#pragma unroll 8
    for (int k = 0; k < 64; k++) {
        const float4 wlv = ((const float4*)(sh_wl + k * 64))[tx];
        const float4 wsv = ((const float4*)(sh_ws + k * 64))[tx];
        float h[4];
#pragma unroll
        for (int j = 0; j < 4; j++) h[j] = sh_h[(r0 + j) * 64 + k];
#pragma unroll
        for (int j = 0; j < 4; j++) {
            accl[j][0] += h[j] * wlv.x; accl[j][1] += h[j] * wlv.y;
            accl[j][2] += h[j] * wlv.z; accl[j][3] += h[j] * wlv.w;
            accs[j][0] += h[j] * wsv.x; accs[j][1] += h[j] * wsv.y;
            accs[j][2] += h[j] * wsv.z; accs[j][3] += h[j] * wsv.w;
        }
    }

    float4 bt;
    bt.x = bl[c0+0] + bs[c0+0] + bias[c0+0];
    bt.y = bl[c0+1] + bs[c0+1] + bias[c0+1];
    bt.z = bl[c0+2] + bs[c0+2] + bias[c0+2];
    bt.w = bl[c0+3] + bs[c0+3] + bias[c0+3];

#pragma unroll
    for (int j = 0; j < 4; j++) {
        int gr = row0 + r0 + j;
        if (gr < NN) {
            __half2 p0 = __floats2half2_rn(accl[j][0], accl[j][1]);
            __half2 p1 = __floats2half2_rn(accl[j][2], accl[j][3]);
            uint2 u = make_uint2(*(unsigned*)&p0, *(unsigned*)&p1);
            ((uint2*)(ylin_dst + gr * 64))[tx] = u;
            float4 hp = make_float4(accs[j][0] + bt.x, accs[j][1] + bt.y,
                                    accs[j][2] + bt.z, accs[j][3] + bt.w);
            ((float4*)(hpre_dst + gr * 64))[tx] = hp;
        }
    }
}

// ============================================================================
// Final gather (layer-5 output slice only, no following GEMM).
// ============================================================================
__global__ void __launch_bounds__(256) gather_relu(int layer, int cur)
{
    const int t = blockIdx.x * 256 + threadIdx.x;
    const int v = t >> 3;
    const int q = t & 7;
    if (v >= NN) return;
    float acc[8] = {};
    gather_node(g_ylin_h[cur], v, q, acc);
    const float* hpre = g_hpre[cur];
    const float4 hp0 = *(const float4*)(hpre + v * 64 + q * 8);
    const float4 hp1 = *(const float4*)(hpre + v * 64 + q * 8 + 4);
    float* outp = g_hcat + (size_t)v * HCATW + layer * UNITS + q * 8;
    float4 o0, o1;
    o0.x = fmaxf(hp0.x + acc[0], 0.f);
    o0.y = fmaxf(hp0.y + acc[1], 0.f);
    o0.z = fmaxf(hp0.z + acc[2], 0.f);
    o0.w = fmaxf(hp0.w + acc[3], 0.f);
    o1.x = fmaxf(hp1.x + acc[4], 0.f);
    o1.y = fmaxf(hp1.y + acc[5], 0.f);
    o1.z = fmaxf(hp1.z + acc[6], 0.f);
    o1.w = fmaxf(hp1.w + acc[7], 0.f);
    *(float4*)(outp)     = o0;
    *(float4*)(outp + 4) = o1;
}

// ============================================================================
// Final: out = hcat @ w_last + b_last   [NN,384] @ [384,40]
// ============================================================================
__global__ void gemm_last(const float* __restrict__ w, const float* __restrict__ b,
                          float* __restrict__ out)
{
    extern __shared__ float sm[];
    float* sh_w = sm;                  // [384][40]
    float* sh_h = sm + HCATW * OUTF;   // [64][64]

    const int tid = threadIdx.x;       // 0..159
    for (int i = tid; i < HCATW * OUTF / 4; i += 160)
        ((float4*)sh_w)[i] = ((const float4*)w)[i];

    const int row0 = blockIdx.x * 64;
    const int tx = tid % 10, ty = tid / 10;
    const int c0 = tx * 4, r0 = ty * 4;
    float acc[4][4] = {};

    for (int kt = 0; kt < HCATW / 64; kt++) {
        __syncthreads();
        for (int i = tid; i < 64 * 16; i += 160) {
            int r = i / 16, kq = i % 16;
            int gr = row0 + r;
            float4 v = make_float4(0.f, 0.f, 0.f, 0.f);
            if (gr < NN) v = *(const float4*)(g_hcat + (size_t)gr * HCATW + kt * 64 + kq * 4);
            ((float4*)(sh_h + r * 64))[kq] = v;
        }
        __syncthreads();
#pragma unroll 8
        for (int kk = 0; kk < 64; kk++) {
            const int k = kt * 64 + kk;
            const float4 wv = ((const float4*)(sh_w + k * OUTF))[tx];
            float h[4];
#pragma unroll
            for (int j = 0; j < 4; j++) h[j] = sh_h[(r0 + j) * 64 + kk];
#pragma unroll
            for (int j = 0; j < 4; j++) {
                acc[j][0] += h[j] * wv.x; acc[j][1] += h[j] * wv.y;
                acc[j][2] += h[j] * wv.z; acc[j][3] += h[j] * wv.w;
            }
        }
    }

    float4 bv = *(const float4*)(b + c0);
#pragma unroll
    for (int j = 0; j < 4; j++) {
        int gr = row0 + r0 + j;
        if (gr < NN) {
            float4 o = make_float4(acc[j][0] + bv.x, acc[j][1] + bv.y,
                                   acc[j][2] + bv.z, acc[j][3] + bv.w);
            *(float4*)(out + (size_t)gr * OUTF + c0) = o;
        }
    }
}

// ============================================================================
extern "C" void kernel_launch(void* const* d_in, const int* in_sizes, int n_in,
                              void* d_out, int out_size)
{
    const float* x      = (const float*)d_in[0];
    const int*   src    = (const int*)  d_in[1];
    const int*   dst    = (const int*)  d_in[2];
    const float* w0l    = (const float*)d_in[3];
    const float* b0l    = (const float*)d_in[4];
    const float* w0s    = (const float*)d_in[5];
    const float* b0s    = (const float*)d_in[6];
    const float* bias0  = (const float*)d_in[7];
    const float* w_lin  = (const float*)d_in[8];
    const float* b_lin  = (const float*)d_in[9];
    const float* w_self = (const float*)d_in[10];
    const float* b_self = (const float*)d_in[11];
    const float* bias   = (const float*)d_in[12];
    const float* w_last = (const float*)d_in[13];
    const float* b_last = (const float*)d_in[14];
    float* out = (float*)d_out;

    const int SMEM0 = (3 * INF * 64) * 4;                       // 98304
    const int SMEMF = (3 * 64 * 64) * 4;                        // 49152
    const int SMEML = (HCATW * OUTF + 64 * 64) * 4;             // 77824

    cudaFuncSetAttribute((const void*)gemm_dual<INF>,
                         cudaFuncAttributeMaxDynamicSharedMemorySize, SMEM0);
    cudaFuncSetAttribute((const void*)fused_gather_gemm,
                         cudaFuncAttributeMaxDynamicSharedMemorySize, SMEMF);
    cudaFuncSetAttribute((const void*)gemm_last,
                         cudaFuncAttributeMaxDynamicSharedMemorySize, SMEML);

    const int nblk     = (NN + 63) / 64;            // 782
    const int eblk     = (NE + 255) / 256;          // 6250
    const int nodeblk  = (NN + 255) / 256;          // 196
    const int gathblk  = (NN * 8 + 255) / 256;      // 1563

    // ---- CSR build (once per launch) ----
    zero_deg<<<nodeblk, 256>>>();
    hist_deg<<<eblk, 256>>>(dst);
    scan_csr<<<1, 1024>>>();
    fill_csr<<<eblk, 256>>>(src, dst);

    // ---- Layer 0 GEMM (input x, K=128) -> buffers[0] ----
    gemm_dual<INF><<<nblk, 256, SMEM0>>>(x, INF, w0l, w0s, b0l, b0s, bias0);

    // ---- Layers 1..5: fused (gather layer l-1 from [cur], GEMM -> [cur^1]) ----
    int cur = 0;
    for (int l = 1; l < NL; l++) {
        const float* wl = w_lin  + (l - 1) * 64 * 64;
        const float* bl = b_lin  + (l - 1) * 64;
        const float* ws = w_self + (l - 1) * 64 * 64;
        const float* bs = b_self + (l - 1) * 64;
        const float* bi = bias   + (l - 1) * 64;
        fused_gather_gemm<<<nblk, 256, SMEMF>>>(l - 1, cur, wl, ws, bl, bs, bi);
        cur ^= 1;
    }

    // ---- Final gather: layer-5 output slice from [cur] ----
    gather_relu<<<gathblk, 256>>>(NL - 1, cur);

    // ---- Final projection ----
    gemm_last<<<nblk, 160, SMEML>>>(w_last, b_last, out);
}

// round 10
// speedup vs baseline: 1.0607x; 1.0393x over previous
#include <cuda_runtime.h>
#include <cuda_fp16.h>
#include <cuda_bf16.h>

#define NN 50000
#define NE 1600000
#define INF 128
#define UNITS 64
#define OUTF 40
#define NL 6
#define HCATW (NL * UNITS)   // 384

// ---- device-global scratch (no allocation allowed) ----
__device__ __half g_ylin_h[NN * UNITS];     // h @ w_lin in fp16 (gather source)
__device__ float  g_hpre[NN * UNITS];       // h @ w_self + (bl+bs+bias), fp32
__device__ float  g_hcat[NN * HCATW];       // relu'd layer outputs (concat buffer)
__device__ int    g_deg[NN];
__device__ int    g_rowptr[NN + 1];
__device__ int    g_cursor[NN];
__device__ int    g_csr_src[NE];

// ============================================================================
// CSR build pieces
// ============================================================================
__global__ void scan_csr()   // 1 block, 1024 threads
{
    __shared__ int sums[1024];
    const int CH = (NN + 1023) / 1024;   // 49
    const int t = threadIdx.x;
    const int base = t * CH;
    int s = 0;
    for (int i = 0; i < CH; i++) {
        int idx = base + i;
        if (idx < NN) s += g_deg[idx];
    }
    sums[t] = s;
    __syncthreads();
    for (int off = 1; off < 1024; off <<= 1) {
        int v = (t >= off) ? sums[t - off] : 0;
        __syncthreads();
        sums[t] += v;
        __syncthreads();
    }
    int run = sums[t] - s;
    for (int i = 0; i < CH; i++) {
        int idx = base + i;
        if (idx < NN) {
            g_rowptr[idx] = run;
            g_cursor[idx] = run;
            run += g_deg[idx];
        }
    }
    if (t == 1023) g_rowptr[NN] = sums[1023];
}

__global__ void fill_csr(const int* __restrict__ src, const int* __restrict__ dst)
{
    int e = blockIdx.x * 256 + threadIdx.x;
    if (e >= NE) return;
    int pos = atomicAdd(&g_cursor[dst[e]], 1);
    g_csr_src[pos] = src[e];
}

// ============================================================================
// Merged kernel: blocks [0, HIST_BLKS) do the degree histogram (grid-stride);
// blocks [HIST_BLKS, HIST_BLKS+GEMM_BLKS) run the layer-0 dual GEMM.
// Both are independent; merging overlaps them on the chip.
//   g_ylin_h = fp16(x @ w0l) ;  g_hpre = x @ w0s + (b0l + b0s + bias0)
// ============================================================================
#define HIST_BLKS 1024
#define GEMM_BLKS ((NN + 63) / 64)   // 782

__global__ void hist_and_gemm0(const int* __restrict__ dst,
                               const float* __restrict__ in,
                               const float* __restrict__ wl, const float* __restrict__ ws,
                               const float* __restrict__ bl, const float* __restrict__ bs,
                               const float* __restrict__ bias)
{
    if (blockIdx.x < HIST_BLKS) {
        // ---- histogram part ----
        for (int e = blockIdx.x * 256 + threadIdx.x; e < NE; e += HIST_BLKS * 256)
            atomicAdd(&g_deg[dst[e]], 1);
        return;
    }

    // ---- layer-0 dual GEMM part (K = INF = 128) ----
    const int K = INF;
    extern __shared__ float sm[];
    float* sh_wl = sm;                 // [K][64]
    float* sh_ws = sm + K * 64;        // [K][64]
    float* sh_h  = sm + 2 * K * 64;    // [64][K]

    const int tid = threadIdx.x;
    for (int i = tid; i < K * 16; i += 256) {
        ((float4*)sh_wl)[i] = ((const float4*)wl)[i];
        ((float4*)sh_ws)[i] = ((const float4*)ws)[i];
    }
    const int row0 = (blockIdx.x - HIST_BLKS) * 64;
    for (int i = tid; i < 64 * (K / 4); i += 256) {
        int r = i / (K / 4), kq = i % (K / 4);
        int gr = row0 + r;
        float4 v = make_float4(0.f, 0.f, 0.f, 0.f);
        if (gr < NN) v = ((const float4*)(in + (size_t)gr * K))[kq];
        ((float4*)(sh_h + r * K))[kq] = v;
    }
    __syncthreads();

    const int tx = tid & 15, ty = tid >> 4;
    const int c0 = tx * 4, r0 = ty * 4;

    float accl[4][4] = {}, accs[4][4] = {};
#pragma unroll 8
    for (int k = 0; k < K; k++) {
        const float4 wlv = ((const float4*)(sh_wl + k * 64))[tx];
        const float4 wsv = ((const float4*)(sh_ws + k * 64))[tx];
        float h[4];
#pragma unroll
        for (int j = 0; j < 4; j++) h[j] = sh_h[(r0 + j) * K + k];
#pragma unroll
        for (int j = 0; j < 4; j++) {
            accl[j][0] += h[j] * wlv.x; accl[j][1] += h[j] * wlv.y;
            accl[j][2] += h[j] * wlv.z; accl[j][3] += h[j] * wlv.w;
            accs[j][0] += h[j] * wsv.x; accs[j][1] += h[j] * wsv.y;
            accs[j][2] += h[j] * wsv.z; accs[j][3] += h[j] * wsv.w;
        }
    }

    float4 bt;
    bt.x = bl[c0+0] + bs[c0+0] + bias[c0+0];
    bt.y = bl[c0+1] + bs[c0+1] + bias[c0+1];
    bt.z = bl[c0+2] + bs[c0+2] + bias[c0+2];
    bt.w = bl[c0+3] + bs[c0+3] + bias[c0+3];

#pragma unroll
    for (int j = 0; j < 4; j++) {
        int gr = row0 + r0 + j;
        if (gr < NN) {
            __half2 p0 = __floats2half2_rn(accl[j][0], accl[j][1]);
            __half2 p1 = __floats2half2_rn(accl[j][2], accl[j][3]);
            uint2 u = make_uint2(*(unsigned*)&p0, *(unsigned*)&p1);
            ((uint2*)(g_ylin_h + gr * 64))[tx] = u;
            float4 hp = make_float4(accs[j][0] + bt.x, accs[j][1] + bt.y,
                                    accs[j][2] + bt.z, accs[j][3] + bt.w);
            ((float4*)(g_hpre + gr * 64))[tx] = hp;
        }
    }
}

// ============================================================================
// Inner-layer dual GEMM (K = 64) — identical to R3.
// ============================================================================
__global__ void gemm_dual64(const float* __restrict__ in, int in_stride,
                            const float* __restrict__ wl, const float* __restrict__ ws,
                            const float* __restrict__ bl, const float* __restrict__ bs,
                            const float* __restrict__ bias)
{
    const int K = 64;
    extern __shared__ float sm[];
    float* sh_wl = sm;                 // [K][64]
    float* sh_ws = sm + K * 64;        // [K][64]
    float* sh_h  = sm + 2 * K * 64;    // [64][K]

    const int tid = threadIdx.x;
    for (int i = tid; i < K * 16; i += 256) {
        ((float4*)sh_wl)[i] = ((const float4*)wl)[i];
        ((float4*)sh_ws)[i] = ((const float4*)ws)[i];
    }
    const int row0 = blockIdx.x * 64;
    for (int i = tid; i < 64 * (K / 4); i += 256) {
        int r = i / (K / 4), kq = i % (K / 4);
        int gr = row0 + r;
        float4 v = make_float4(0.f, 0.f, 0.f, 0.f);
        if (gr < NN) v = ((const float4*)(in + (size_t)gr * in_stride))[kq];
        ((float4*)(sh_h + r * K))[kq] = v;
    }
    __syncthreads();

    const int tx = tid & 15, ty = tid >> 4;
    const int c0 = tx * 4, r0 = ty * 4;

    float accl[4][4] = {}, accs[4][4] = {};
#pragma unroll 8
    for (int k = 0; k < K; k++) {
        const float4 wlv = ((const float4*)(sh_wl + k * 64))[tx];
        const float4 wsv = ((const float4*)(sh_ws + k * 64))[tx];
        float h[4];
#pragma unroll
        for (int j = 0; j < 4; j++) h[j] = sh_h[(r0 + j) * K + k];
#pragma unroll
        for (int j = 0; j < 4; j++) {
            accl[j][0] += h[j] * wlv.x; accl[j][1] += h[j] * wlv.y;
            accl[j][2] += h[j] * wlv.z; accl[j][3] += h[j] * wlv.w;
            accs[j][0] += h[j] * wsv.x; accs[j][1] += h[j] * wsv.y;
            accs[j][2] += h[j] * wsv.z; accs[j][3] += h[j] * wsv.w;
        }
    }

    float4 bt;
    bt.x = bl[c0+0] + bs[c0+0] + bias[c0+0];
    bt.y = bl[c0+1] + bs[c0+1] + bias[c0+1];
    bt.z = bl[c0+2] + bs[c0+2] + bias[c0+2];
    bt.w = bl[c0+3] + bs[c0+3] + bias[c0+3];

#pragma unroll
    for (int j = 0; j < 4; j++) {
        int gr = row0 + r0 + j;
        if (gr < NN) {
            __half2 p0 = __floats2half2_rn(accl[j][0], accl[j][1]);
            __half2 p1 = __floats2half2_rn(accl[j][2], accl[j][3]);
            uint2 u = make_uint2(*(unsigned*)&p0, *(unsigned*)&p1);
            ((uint2*)(g_ylin_h + gr * 64))[tx] = u;
            float4 hp = make_float4(accs[j][0] + bt.x, accs[j][1] + bt.y,
                                    accs[j][2] + bt.z, accs[j][3] + bt.w);
            ((float4*)(g_hpre + gr * 64))[tx] = hp;
        }
    }
}

// ============================================================================
// Gather: software-pipelined — prefetch next batch's indices before
// accumulating the current batch, overlapping idx latency with row latency.
// ============================================================================
__device__ __forceinline__ void acc8(float* acc, uint4 u)
{
    float2 f;
    f = __half22float2(*(__half2*)&u.x); acc[0] += f.x; acc[1] += f.y;
    f = __half22float2(*(__half2*)&u.y); acc[2] += f.x; acc[3] += f.y;
    f = __half22float2(*(__half2*)&u.z); acc[4] += f.x; acc[5] += f.y;
    f = __half22float2(*(__half2*)&u.w); acc[6] += f.x; acc[7] += f.y;
}

__device__ __forceinline__ void gather_node(int v, int q, float* acc)
{
    const int beg = g_rowptr[v];
    const int end = g_rowptr[v + 1];
    const uint4* base = (const uint4*)g_ylin_h;   // 8 uint4 per node row
    int e = beg;
    if (e + 4 <= end) {
        int i0 = g_csr_src[e + 0];
        int i1 = g_csr_src[e + 1];
        int i2 = g_csr_src[e + 2];
        int i3 = g_csr_src[e + 3];
        while (e + 8 <= end) {
            uint4 a = base[i0 * 8 + q];
            uint4 b = base[i1 * 8 + q];
            uint4 c = base[i2 * 8 + q];
            uint4 d = base[i3 * 8 + q];
            i0 = g_csr_src[e + 4];
            i1 = g_csr_src[e + 5];
            i2 = g_csr_src[e + 6];
            i3 = g_csr_src[e + 7];
            acc8(acc, a); acc8(acc, b); acc8(acc, c); acc8(acc, d);
            e += 4;
        }
        {   // drain the prefetched batch
            uint4 a = base[i0 * 8 + q];
            uint4 b = base[i1 * 8 + q];
            uint4 c = base[i2 * 8 + q];
            uint4 d = base[i3 * 8 + q];
            acc8(acc, a); acc8(acc, b); acc8(acc, c); acc8(acc, d);
            e += 4;
        }
    }
    for (; e < end; e++) {
        int s = g_csr_src[e];
        acc8(acc, base[s * 8 + q]);
    }
}

__global__ void __launch_bounds__(256) gather_relu(int layer)
{
    const int t = blockIdx.x * 256 + threadIdx.x;
    const int v = t >> 3;
    const int q = t & 7;
    if (v >= NN) return;
    float acc[8] = {};
    gather_node(v, q, acc);
    const float4 hp0 = *(const float4*)(g_hpre + v * 64 + q * 8);
    const float4 hp1 = *(const float4*)(g_hpre + v * 64 + q * 8 + 4);
    float* outp = g_hcat + (size_t)v * HCATW + layer * UNITS + q * 8;
    float4 o0, o1;
    o0.x = fmaxf(hp0.x + acc[0], 0.f);
    o0.y = fmaxf(hp0.y + acc[1], 0.f);
    o0.z = fmaxf(hp0.z + acc[2], 0.f);
    o0.w = fmaxf(hp0.w + acc[3], 0.f);
    o1.x = fmaxf(hp1.x + acc[4], 0.f);
    o1.y = fmaxf(hp1.y + acc[5], 0.f);
    o1.z = fmaxf(hp1.z + acc[6], 0.f);
    o1.w = fmaxf(hp1.w + acc[7], 0.f);
    *(float4*)(outp)     = o0;
    *(float4*)(outp + 4) = o1;
}

// ============================================================================
// Final: out = hcat @ w_last + b_last   [NN,384] @ [384,40]
// ============================================================================
__global__ void gemm_last(const float* __restrict__ w, const float* __restrict__ b,
                          float* __restrict__ out)
{
    extern __shared__ float sm[];
    float* sh_w = sm;                  // [384][40]
    float* sh_h = sm + HCATW * OUTF;   // [64][64]

    const int tid = threadIdx.x;       // 0..159
    for (int i = tid; i < HCATW * OUTF / 4; i += 160)
        ((float4*)sh_w)[i] = ((const float4*)w)[i];

    const int row0 = blockIdx.x * 64;
    const int tx = tid % 10, ty = tid / 10;
    const int c0 = tx * 4, r0 = ty * 4;
    float acc[4][4] = {};

    for (int kt = 0; kt < HCATW / 64; kt++) {
        __syncthreads();
        for (int i = tid; i < 64 * 16; i += 160) {
            int r = i / 16, kq = i % 16;
            int gr = row0 + r;
            float4 v = make_float4(0.f, 0.f, 0.f, 0.f);
            if (gr < NN) v = *(const float4*)(g_hcat + (size_t)gr * HCATW + kt * 64 + kq * 4);
            ((float4*)(sh_h + r * 64))[kq] = v;
        }
        __syncthreads();
#pragma unroll 8
        for (int kk = 0; kk < 64; kk++) {
            const int k = kt * 64 + kk;
            const float4 wv = ((const float4*)(sh_w + k * OUTF))[tx];
            float h[4];
#pragma unroll
            for (int j = 0; j < 4; j++) h[j] = sh_h[(r0 + j) * 64 + kk];
#pragma unroll
            for (int j = 0; j < 4; j++) {
                acc[j][0] += h[j] * wv.x; acc[j][1] += h[j] * wv.y;
                acc[j][2] += h[j] * wv.z; acc[j][3] += h[j] * wv.w;
            }
        }
    }

    float4 bv = *(const float4*)(b + c0);
#pragma unroll
    for (int j = 0; j < 4; j++) {
        int gr = row0 + r0 + j;
        if (gr < NN) {
            float4 o = make_float4(acc[j][0] + bv.x, acc[j][1] + bv.y,
                                   acc[j][2] + bv.z, acc[j][3] + bv.w);
            *(float4*)(out + (size_t)gr * OUTF + c0) = o;
        }
    }
}

// ============================================================================
extern "C" void kernel_launch(void* const* d_in, const int* in_sizes, int n_in,
                              void* d_out, int out_size)
{
    const float* x      = (const float*)d_in[0];
    const int*   src    = (const int*)  d_in[1];
    const int*   dst    = (const int*)  d_in[2];
    const float* w0l    = (const float*)d_in[3];
    const float* b0l    = (const float*)d_in[4];
    const float* w0s    = (const float*)d_in[5];
    const float* b0s    = (const float*)d_in[6];
    const float* bias0  = (const float*)d_in[7];
    const float* w_lin  = (const float*)d_in[8];
    const float* b_lin  = (const float*)d_in[9];
    const float* w_self = (const float*)d_in[10];
    const float* b_self = (const float*)d_in[11];
    const float* bias   = (const float*)d_in[12];
    const float* w_last = (const float*)d_in[13];
    const float* b_last = (const float*)d_in[14];
    float* out = (float*)d_out;

    const int SMEM0 = (3 * INF * 64) * 4;                       // 98304
    const int SMEM1 = (3 * 64 * 64) * 4;                        // 49152
    const int SMEML = (HCATW * OUTF + 64 * 64) * 4;             // 77824

    cudaFuncSetAttribute((const void*)hist_and_gemm0,
                         cudaFuncAttributeMaxDynamicSharedMemorySize, SMEM0);
    cudaFuncSetAttribute((const void*)gemm_dual64,
                         cudaFuncAttributeMaxDynamicSharedMemorySize, SMEM1);
    cudaFuncSetAttribute((const void*)gemm_last,
                         cudaFuncAttributeMaxDynamicSharedMemorySize, SMEML);

    void* hcat_p = nullptr;
    cudaGetSymbolAddress(&hcat_p, g_hcat);
    const float* hcat = (const float*)hcat_p;
    void* deg_p = nullptr;
    cudaGetSymbolAddress(&deg_p, g_deg);

    const int nblk     = (NN + 63) / 64;            // 782
    const int eblk     = (NE + 255) / 256;          // 6250
    const int gathblk  = (NN * 8 + 255) / 256;      // 1563

    // ---- CSR build overlapped with layer-0 GEMM ----
    cudaMemsetAsync(deg_p, 0, NN * sizeof(int));
    hist_and_gemm0<<<HIST_BLKS + GEMM_BLKS, 256, SMEM0>>>(
        dst, x, w0l, w0s, b0l, b0s, bias0);
    scan_csr<<<1, 1024>>>();
    fill_csr<<<eblk, 256>>>(src, dst);

    // ---- Layer 0 gather ----
    gather_relu<<<gathblk, 256>>>(0);

    // ---- Layers 1..5 ----
    for (int l = 1; l < NL; l++) {
        const float* in = hcat + (l - 1) * UNITS;
        const float* wl = w_lin  + (l - 1) * 64 * 64;
        const float* bl = b_lin  + (l - 1) * 64;
        const float* ws = w_self + (l - 1) * 64 * 64;
        const float* bs = b_self + (l - 1) * 64;
        const float* bi = bias   + (l - 1) * 64;
        gemm_dual64<<<nblk, 256, SMEM1>>>(in, HCATW, wl, ws, bl, bs, bi);
        gather_relu<<<gathblk, 256>>>(l);
    }

    // ---- Final projection ----
    gemm_last<<<nblk, 160, SMEML>>>(w_last, b_last, out);
}

// round 14
// speedup vs baseline: 1.0683x; 1.0072x over previous
#include <cuda_runtime.h>
#include <cuda_fp16.h>
#include <cuda_bf16.h>

#define NN 50000
#define NE 1600000
#define INF 128
#define UNITS 64
#define OUTF 40
#define NL 6
#define HCATW (NL * UNITS)   // 384

// ---- device-global scratch (no allocation allowed) ----
__device__ __half g_ylin_h[NN * UNITS];     // h @ w_lin in fp16 (gather source)
__device__ float  g_hpre[NN * UNITS];       // h @ w_self + (bl+bs+bias), fp32
__device__ float  g_hcat[NN * HCATW];       // relu'd layer outputs (concat buffer)
__device__ int    g_deg[NN];
__device__ int    g_rowptr[NN + 1];
__device__ int    g_cursor[NN];
__device__ int    g_csr_src[NE];

// ============================================================================
// CSR build pieces (R10, known good)
// ============================================================================
__global__ void scan_csr()   // 1 block, 1024 threads
{
    __shared__ int sums[1024];
    const int CH = (NN + 1023) / 1024;   // 49
    const int t = threadIdx.x;
    const int base = t * CH;
    int s = 0;
    for (int i = 0; i < CH; i++) {
        int idx = base + i;
        if (idx < NN) s += g_deg[idx];
    }
    sums[t] = s;
    __syncthreads();
    for (int off = 1; off < 1024; off <<= 1) {
        int v = (t >= off) ? sums[t - off] : 0;
        __syncthreads();
        sums[t] += v;
        __syncthreads();
    }
    int run = sums[t] - s;
    for (int i = 0; i < CH; i++) {
        int idx = base + i;
        if (idx < NN) {
            g_rowptr[idx] = run;
            g_cursor[idx] = run;
            run += g_deg[idx];
        }
    }
    if (t == 1023) g_rowptr[NN] = sums[1023];
}

__global__ void fill_csr(const int* __restrict__ src, const int* __restrict__ dst)
{
    int e = blockIdx.x * 256 + threadIdx.x;
    if (e >= NE) return;
    int pos = atomicAdd(&g_cursor[dst[e]], 1);
    g_csr_src[pos] = src[e];
}

// ============================================================================
// Merged kernel: blocks [0, HIST_BLKS) histogram; rest = layer-0 dual GEMM.
// GEMM inner loop: k unrolled by 4, h fetched as LDS.128 per row.
// ============================================================================
#define HIST_BLKS 1024
#define GEMM_BLKS ((NN + 63) / 64)   // 782

__global__ void hist_and_gemm0(const int* __restrict__ dst,
                               const float* __restrict__ in,
                               const float* __restrict__ wl, const float* __restrict__ ws,
                               const float* __restrict__ bl, const float* __restrict__ bs,
                               const float* __restrict__ bias)
{
    if (blockIdx.x < HIST_BLKS) {
        for (int e = blockIdx.x * 256 + threadIdx.x; e < NE; e += HIST_BLKS * 256)
            atomicAdd(&g_deg[dst[e]], 1);
        return;
    }

    const int K = INF;
    extern __shared__ float sm[];
    float* sh_wl = sm;                 // [K][64]
    float* sh_ws = sm + K * 64;        // [K][64]
    float* sh_h  = sm + 2 * K * 64;    // [64][K]

    const int tid = threadIdx.x;
    for (int i = tid; i < K * 16; i += 256) {
        ((float4*)sh_wl)[i] = ((const float4*)wl)[i];
        ((float4*)sh_ws)[i] = ((const float4*)ws)[i];
    }
    const int row0 = (blockIdx.x - HIST_BLKS) * 64;
    for (int i = tid; i < 64 * (K / 4); i += 256) {
        int r = i / (K / 4), kq = i % (K / 4);
        int gr = row0 + r;
        float4 v = make_float4(0.f, 0.f, 0.f, 0.f);
        if (gr < NN) v = ((const float4*)(in + (size_t)gr * K))[kq];
        ((float4*)(sh_h + r * K))[kq] = v;
    }
    __syncthreads();

    const int tx = tid & 15, ty = tid >> 4;
    const int c0 = tx * 4, r0 = ty * 4;

    float accl[4][4] = {}, accs[4][4] = {};
#pragma unroll 4
    for (int k0 = 0; k0 < K; k0 += 4) {
        float hh[4][4];
#pragma unroll
        for (int j = 0; j < 4; j++) {
            float4 hv = *(const float4*)(sh_h + (r0 + j) * K + k0);
            hh[j][0] = hv.x; hh[j][1] = hv.y; hh[j][2] = hv.z; hh[j][3] = hv.w;
        }
#pragma unroll
        for (int kk = 0; kk < 4; kk++) {
            const float4 wlv = ((const float4*)(sh_wl + (k0 + kk) * 64))[tx];
            const float4 wsv = ((const float4*)(sh_ws + (k0 + kk) * 64))[tx];
#pragma unroll
            for (int j = 0; j < 4; j++) {
                const float h = hh[j][kk];
                accl[j][0] += h * wlv.x; accl[j][1] += h * wlv.y;
                accl[j][2] += h * wlv.z; accl[j][3] += h * wlv.w;
                accs[j][0] += h * wsv.x; accs[j][1] += h * wsv.y;
                accs[j][2] += h * wsv.z; accs[j][3] += h * wsv.w;
            }
        }
    }

    float4 bt;
    bt.x = bl[c0+0] + bs[c0+0] + bias[c0+0];
    bt.y = bl[c0+1] + bs[c0+1] + bias[c0+1];
    bt.z = bl[c0+2] + bs[c0+2] + bias[c0+2];
    bt.w = bl[c0+3] + bs[c0+3] + bias[c0+3];

#pragma unroll
    for (int j = 0; j < 4; j++) {
        int gr = row0 + r0 + j;
        if (gr < NN) {
            __half2 p0 = __floats2half2_rn(accl[j][0], accl[j][1]);
            __half2 p1 = __floats2half2_rn(accl[j][2], accl[j][3]);
            uint2 u = make_uint2(*(unsigned*)&p0, *(unsigned*)&p1);
            ((uint2*)(g_ylin_h + gr * 64))[tx] = u;
            float4 hp = make_float4(accs[j][0] + bt.x, accs[j][1] + bt.y,
                                    accs[j][2] + bt.z, accs[j][3] + bt.w);
            ((float4*)(g_hpre + gr * 64))[tx] = hp;
        }
    }
}

// ============================================================================
// Inner-layer dual GEMM (K = 64): k unrolled by 4, h via LDS.128.
// ============================================================================
__global__ void __launch_bounds__(256) gemm_dual64(
    const float* __restrict__ in, int in_stride,
    const float* __restrict__ wl, const float* __restrict__ ws,
    const float* __restrict__ bl, const float* __restrict__ bs,
    const float* __restrict__ bias)
{
    const int K = 64;
    extern __shared__ float sm[];
    float* sh_wl = sm;                 // [K][64]
    float* sh_ws = sm + K * 64;        // [K][64]
    float* sh_h  = sm + 2 * K * 64;    // [64][K]

    const int tid = threadIdx.x;
    for (int i = tid; i < K * 16; i += 256) {
        ((float4*)sh_wl)[i] = ((const float4*)wl)[i];
        ((float4*)sh_ws)[i] = ((const float4*)ws)[i];
    }
    const int row0 = blockIdx.x * 64;
    for (int i = tid; i < 64 * (K / 4); i += 256) {
        int r = i / (K / 4), kq = i % (K / 4);
        int gr = row0 + r;
        float4 v = make_float4(0.f, 0.f, 0.f, 0.f);
        if (gr < NN) v = ((const float4*)(in + (size_t)gr * in_stride))[kq];
        ((float4*)(sh_h + r * K))[kq] = v;
    }
    __syncthreads();

    const int tx = tid & 15, ty = tid >> 4;
    const int c0 = tx * 4, r0 = ty * 4;

    float accl[4][4] = {}, accs[4][4] = {};
#pragma unroll 4
    for (int k0 = 0; k0 < K; k0 += 4) {
        float hh[4][4];
#pragma unroll
        for (int j = 0; j < 4; j++) {
            float4 hv = *(const float4*)(sh_h + (r0 + j) * K + k0);
            hh[j][0] = hv.x; hh[j][1] = hv.y; hh[j][2] = hv.z; hh[j][3] = hv.w;
        }
#pragma unroll
        for (int kk = 0; kk < 4; kk++) {
            const float4 wlv = ((const float4*)(sh_wl + (k0 + kk) * 64))[tx];
            const float4 wsv = ((const float4*)(sh_ws + (k0 + kk) * 64))[tx];
#pragma unroll
            for (int j = 0; j < 4; j++) {
                const float h = hh[j][kk];
                accl[j][0] += h * wlv.x; accl[j][1] += h * wlv.y;
                accl[j][2] += h * wlv.z; accl[j][3] += h * wlv.w;
                accs[j][0] += h * wsv.x; accs[j][1] += h * wsv.y;
                accs[j][2] += h * wsv.z; accs[j][3] += h * wsv.w;
            }
        }
    }

    float4 bt;
    bt.x = bl[c0+0] + bs[c0+0] + bias[c0+0];
    bt.y = bl[c0+1] + bs[c0+1] + bias[c0+1];
    bt.z = bl[c0+2] + bs[c0+2] + bias[c0+2];
    bt.w = bl[c0+3] + bs[c0+3] + bias[c0+3];

#pragma unroll
    for (int j = 0; j < 4; j++) {
        int gr = row0 + r0 + j;
        if (gr < NN) {
            __half2 p0 = __floats2half2_rn(accl[j][0], accl[j][1]);
            __half2 p1 = __floats2half2_rn(accl[j][2], accl[j][3]);
            uint2 u = make_uint2(*(unsigned*)&p0, *(unsigned*)&p1);
            ((uint2*)(g_ylin_h + gr * 64))[tx] = u;
            float4 hp = make_float4(accs[j][0] + bt.x, accs[j][1] + bt.y,
                                    accs[j][2] + bt.z, accs[j][3] + bt.w);
            ((float4*)(g_hpre + gr * 64))[tx] = hp;
        }
    }
}

// ============================================================================
// Gather (R10, known good): pipelined index prefetch, fp32 accumulate.
// ============================================================================
__device__ __forceinline__ void acc8(float* acc, uint4 u)
{
    float2 f;
    f = __half22float2(*(__half2*)&u.x); acc[0] += f.x; acc[1] += f.y;
    f = __half22float2(*(__half2*)&u.y); acc[2] += f.x; acc[3] += f.y;
    f = __half22float2(*(__half2*)&u.z); acc[4] += f.x; acc[5] += f.y;
    f = __half22float2(*(__half2*)&u.w); acc[6] += f.x; acc[7] += f.y;
}

__device__ __forceinline__ void gather_node(int v, int q, float* acc)
{
    const int beg = g_rowptr[v];
    const int end = g_rowptr[v + 1];
    const uint4* base = (const uint4*)g_ylin_h;   // 8 uint4 per node row
    int e = beg;
    if (e + 4 <= end) {
        int i0 = g_csr_src[e + 0];
        int i1 = g_csr_src[e + 1];
        int i2 = g_csr_src[e + 2];
        int i3 = g_csr_src[e + 3];
        while (e + 8 <= end) {
            uint4 a = base[i0 * 8 + q];
            uint4 b = base[i1 * 8 + q];
            uint4 c = base[i2 * 8 + q];
            uint4 d = base[i3 * 8 + q];
            i0 = g_csr_src[e + 4];
            i1 = g_csr_src[e + 5];
            i2 = g_csr_src[e + 6];
            i3 = g_csr_src[e + 7];
            acc8(acc, a); acc8(acc, b); acc8(acc, c); acc8(acc, d);
            e += 4;
        }
        {
            uint4 a = base[i0 * 8 + q];
            uint4 b = base[i1 * 8 + q];
            uint4 c = base[i2 * 8 + q];
            uint4 d = base[i3 * 8 + q];
            acc8(acc, a); acc8(acc, b); acc8(acc, c); acc8(acc, d);
            e += 4;
        }
    }
    for (; e < end; e++) {
        int s = g_csr_src[e];
        acc8(acc, base[s * 8 + q]);
    }
}

__global__ void __launch_bounds__(256) gather_relu(int layer)
{
    const int t = blockIdx.x * 256 + threadIdx.x;
    const int v = t >> 3;
    const int q = t & 7;
    if (v >= NN) return;
    float acc[8] = {};
    gather_node(v, q, acc);
    const float4 hp0 = *(const float4*)(g_hpre + v * 64 + q * 8);
    const float4 hp1 = *(const float4*)(g_hpre + v * 64 + q * 8 + 4);
    float* outp = g_hcat + (size_t)v * HCATW + layer * UNITS + q * 8;
    float4 o0, o1;
    o0.x = fmaxf(hp0.x + acc[0], 0.f);
    o0.y = fmaxf(hp0.y + acc[1], 0.f);
    o0.z = fmaxf(hp0.z + acc[2], 0.f);
    o0.w = fmaxf(hp0.w + acc[3], 0.f);
    o1.x = fmaxf(hp1.x + acc[4], 0.f);
    o1.y = fmaxf(hp1.y + acc[5], 0.f);
    o1.z = fmaxf(hp1.z + acc[6], 0.f);
    o1.w = fmaxf(hp1.w + acc[7], 0.f);
    *(float4*)(outp)     = o0;
    *(float4*)(outp + 4) = o1;
}

// ============================================================================
// Final: out = hcat @ w_last + b_last   [NN,384] @ [384,40]
// k unrolled by 4, h via LDS.128.
// ============================================================================
__global__ void gemm_last(const float* __restrict__ w, const float* __restrict__ b,
                          float* __restrict__ out)
{
    extern __shared__ float sm[];
    float* sh_w = sm;                  // [384][40]
    float* sh_h = sm + HCATW * OUTF;   // [64][64]

    const int tid = threadIdx.x;       // 0..159
    for (int i = tid; i < HCATW * OUTF / 4; i += 160)
        ((float4*)sh_w)[i] = ((const float4*)w)[i];

    const int row0 = blockIdx.x * 64;
    const int tx = tid % 10, ty = tid / 10;
    const int c0 = tx * 4, r0 = ty * 4;
    float acc[4][4] = {};

    for (int kt = 0; kt < HCATW / 64; kt++) {
        __syncthreads();
        for (int i = tid; i < 64 * 16; i += 160) {
            int r = i / 16, kq = i % 16;
            int gr = row0 + r;
            float4 v = make_float4(0.f, 0.f, 0.f, 0.f);
            if (gr < NN) v = *(const float4*)(g_hcat + (size_t)gr * HCATW + kt * 64 + kq * 4);
            ((float4*)(sh_h + r * 64))[kq] = v;
        }
        __syncthreads();
#pragma unroll 4
        for (int k0 = 0; k0 < 64; k0 += 4) {
            float hh[4][4];
#pragma unroll
            for (int j = 0; j < 4; j++) {
                float4 hv = *(const float4*)(sh_h + (r0 + j) * 64 + k0);
                hh[j][0] = hv.x; hh[j][1] = hv.y; hh[j][2] = hv.z; hh[j][3] = hv.w;
            }
#pragma unroll
            for (int kk = 0; kk < 4; kk++) {
                const int k = kt * 64 + k0 + kk;
                const float4 wv = ((const float4*)(sh_w + k * OUTF))[tx];
#pragma unroll
                for (int j = 0; j < 4; j++) {
                    const float h = hh[j][kk];
                    acc[j][0] += h * wv.x; acc[j][1] += h * wv.y;
                    acc[j][2] += h * wv.z; acc[j][3] += h * wv.w;
                }
            }
        }
    }

    float4 bv = *(const float4*)(b + c0);
#pragma unroll
    for (int j = 0; j < 4; j++) {
        int gr = row0 + r0 + j;
        if (gr < NN) {
            float4 o = make_float4(acc[j][0] + bv.x, acc[j][1] + bv.y,
                                   acc[j][2] + bv.z, acc[j][3] + bv.w);
            *(float4*)(out + (size_t)gr * OUTF + c0) = o;
        }
    }
}

// ============================================================================
extern "C" void kernel_launch(void* const* d_in, const int* in_sizes, int n_in,
                              void* d_out, int out_size)
{
    const float* x      = (const float*)d_in[0];
    const int*   src    = (const int*)  d_in[1];
    const int*   dst    = (const int*)  d_in[2];
    const float* w0l    = (const float*)d_in[3];
    const float* b0l    = (const float*)d_in[4];
    const float* w0s    = (const float*)d_in[5];
    const float* b0s    = (const float*)d_in[6];
    const float* bias0  = (const float*)d_in[7];
    const float* w_lin  = (const float*)d_in[8];
    const float* b_lin  = (const float*)d_in[9];
    const float* w_self = (const float*)d_in[10];
    const float* b_self = (const float*)d_in[11];
    const float* bias   = (const float*)d_in[12];
    const float* w_last = (const float*)d_in[13];
    const float* b_last = (const float*)d_in[14];
    float* out = (float*)d_out;

    const int SMEM0 = (3 * INF * 64) * 4;                       // 98304
    const int SMEM1 = (3 * 64 * 64) * 4;                        // 49152
    const int SMEML = (HCATW * OUTF + 64 * 64) * 4;             // 77824

    cudaFuncSetAttribute((const void*)hist_and_gemm0,
                         cudaFuncAttributeMaxDynamicSharedMemorySize, SMEM0);
    cudaFuncSetAttribute((const void*)gemm_dual64,
                         cudaFuncAttributeMaxDynamicSharedMemorySize, SMEM1);
    cudaFuncSetAttribute((const void*)gemm_last,
                         cudaFuncAttributeMaxDynamicSharedMemorySize, SMEML);

    void* hcat_p = nullptr;
    cudaGetSymbolAddress(&hcat_p, g_hcat);
    const float* hcat = (const float*)hcat_p;
    void* deg_p = nullptr;
    cudaGetSymbolAddress(&deg_p, g_deg);

    const int nblk     = (NN + 63) / 64;            // 782
    const int eblk     = (NE + 255) / 256;          // 6250
    const int gathblk  = (NN * 8 + 255) / 256;      // 1563

    // ---- CSR build overlapped with layer-0 GEMM ----
    cudaMemsetAsync(deg_p, 0, NN * sizeof(int));
    hist_and_gemm0<<<HIST_BLKS + GEMM_BLKS, 256, SMEM0>>>(
        dst, x, w0l, w0s, b0l, b0s, bias0);
    scan_csr<<<1, 1024>>>();
    fill_csr<<<eblk, 256>>>(src, dst);

    // ---- Layer 0 gather ----
    gather_relu<<<gathblk, 256>>>(0);

    // ---- Layers 1..5 ----
    for (int l = 1; l < NL; l++) {
        const float* in = hcat + (l - 1) * UNITS;
        const float* wl = w_lin  + (l - 1) * 64 * 64;
        const float* bl = b_lin  + (l - 1) * 64;
        const float* ws = w_self + (l - 1) * 64 * 64;
        const float* bs = b_self + (l - 1) * 64;
        const float* bi = bias   + (l - 1) * 64;
        gemm_dual64<<<nblk, 256, SMEM1>>>(in, HCATW, wl, ws, bl, bs, bi);
        gather_relu<<<gathblk, 256>>>(l);
    }

    // ---- Final projection ----
    gemm_last<<<nblk, 160, SMEML>>>(w_last, b_last, out);
}

// round 16
// speedup vs baseline: 1.1556x; 1.0816x over previous
#include <cuda_runtime.h>
#include <cuda_fp16.h>
#include <cuda_bf16.h>

#define NN 50000
#define NE 1600000
#define INF 128
#define UNITS 64
#define OUTF 40
#define NL 6
#define HCATW (NL * UNITS)   // 384

// ---- device-global scratch (no allocation allowed) ----
__device__ __half g_ylin_h[NN * UNITS];     // h @ w_lin in fp16 (gather source)
__device__ float  g_hpre[NN * UNITS];       // h @ w_self + (bl+bs+bias), fp32
__device__ float  g_hcat[NN * HCATW];       // relu'd layer outputs, fp32 (fp16 overflows!)
__device__ int    g_deg[NN];
__device__ int    g_rowptr[NN + 1];
__device__ int    g_cursor[NN];
__device__ int    g_csr_src[NE];

// ============================================================================
// CSR build pieces (known good)
// ============================================================================
__global__ void scan_csr()   // 1 block, 1024 threads
{
    __shared__ int sums[1024];
    const int CH = (NN + 1023) / 1024;   // 49
    const int t = threadIdx.x;
    const int base = t * CH;
    int s = 0;
    for (int i = 0; i < CH; i++) {
        int idx = base + i;
        if (idx < NN) s += g_deg[idx];
    }
    sums[t] = s;
    __syncthreads();
    for (int off = 1; off < 1024; off <<= 1) {
        int v = (t >= off) ? sums[t - off] : 0;
        __syncthreads();
        sums[t] += v;
        __syncthreads();
    }
    int run = sums[t] - s;
    for (int i = 0; i < CH; i++) {
        int idx = base + i;
        if (idx < NN) {
            g_rowptr[idx] = run;
            g_cursor[idx] = run;
            run += g_deg[idx];
        }
    }
    if (t == 1023) g_rowptr[NN] = sums[1023];
}

__global__ void fill_csr(const int* __restrict__ src, const int* __restrict__ dst)
{
    int e = blockIdx.x * 256 + threadIdx.x;
    if (e >= NE) return;
    int pos = atomicAdd(&g_cursor[dst[e]], 1);
    g_csr_src[pos] = src[e];
}

// ============================================================================
// Merged kernel: blocks [0, HIST_BLKS) histogram; rest = layer-0 dual GEMM.
// ============================================================================
#define HIST_BLKS 1024
#define GEMM_BLKS ((NN + 63) / 64)   // 782

__global__ void hist_and_gemm0(const int* __restrict__ dst,
                               const float* __restrict__ in,
                               const float* __restrict__ wl, const float* __restrict__ ws,
                               const float* __restrict__ bl, const float* __restrict__ bs,
                               const float* __restrict__ bias)
{
    if (blockIdx.x < HIST_BLKS) {
        for (int e = blockIdx.x * 256 + threadIdx.x; e < NE; e += HIST_BLKS * 256)
            atomicAdd(&g_deg[dst[e]], 1);
        return;
    }

    const int K = INF;
    extern __shared__ float sm[];
    float* sh_wl = sm;                 // [K][64]
    float* sh_ws = sm + K * 64;        // [K][64]
    float* sh_h  = sm + 2 * K * 64;    // [64][K]

    const int tid = threadIdx.x;
    for (int i = tid; i < K * 16; i += 256) {
        ((float4*)sh_wl)[i] = ((const float4*)wl)[i];
        ((float4*)sh_ws)[i] = ((const float4*)ws)[i];
    }
    const int row0 = (blockIdx.x - HIST_BLKS) * 64;
    for (int i = tid; i < 64 * (K / 4); i += 256) {
        int r = i / (K / 4), kq = i % (K / 4);
        int gr = row0 + r;
        float4 v = make_float4(0.f, 0.f, 0.f, 0.f);
        if (gr < NN) v = ((const float4*)(in + (size_t)gr * K))[kq];
        ((float4*)(sh_h + r * K))[kq] = v;
    }
    __syncthreads();

    const int tx = tid & 15, ty = tid >> 4;
    const int c0 = tx * 4, r0 = ty * 4;

    float accl[4][4] = {}, accs[4][4] = {};
#pragma unroll 4
    for (int k0 = 0; k0 < K; k0 += 4) {
        float hh[4][4];
#pragma unroll
        for (int j = 0; j < 4; j++) {
            float4 hv = *(const float4*)(sh_h + (r0 + j) * K + k0);
            hh[j][0] = hv.x; hh[j][1] = hv.y; hh[j][2] = hv.z; hh[j][3] = hv.w;
        }
#pragma unroll
        for (int kk = 0; kk < 4; kk++) {
            const float4 wlv = ((const float4*)(sh_wl + (k0 + kk) * 64))[tx];
            const float4 wsv = ((const float4*)(sh_ws + (k0 + kk) * 64))[tx];
#pragma unroll
            for (int j = 0; j < 4; j++) {
                const float h = hh[j][kk];
                accl[j][0] += h * wlv.x; accl[j][1] += h * wlv.y;
                accl[j][2] += h * wlv.z; accl[j][3] += h * wlv.w;
                accs[j][0] += h * wsv.x; accs[j][1] += h * wsv.y;
                accs[j][2] += h * wsv.z; accs[j][3] += h * wsv.w;
            }
        }
    }

    float4 bt;
    bt.x = bl[c0+0] + bs[c0+0] + bias[c0+0];
    bt.y = bl[c0+1] + bs[c0+1] + bias[c0+1];
    bt.z = bl[c0+2] + bs[c0+2] + bias[c0+2];
    bt.w = bl[c0+3] + bs[c0+3] + bias[c0+3];

#pragma unroll
    for (int j = 0; j < 4; j++) {
        int gr = row0 + r0 + j;
        if (gr < NN) {
            __half2 p0 = __floats2half2_rn(accl[j][0], accl[j][1]);
            __half2 p1 = __floats2half2_rn(accl[j][2], accl[j][3]);
            uint2 u = make_uint2(*(unsigned*)&p0, *(unsigned*)&p1);
            ((uint2*)(g_ylin_h + gr * 64))[tx] = u;
            float4 hp = make_float4(accs[j][0] + bt.x, accs[j][1] + bt.y,
                                    accs[j][2] + bt.z, accs[j][3] + bt.w);
            ((float4*)(g_hpre + gr * 64))[tx] = hp;
        }
    }
}

// ============================================================================
// Inner-layer dual GEMM (K = 64): fp32 in from hcat slice (R14, known good).
// ============================================================================
__global__ void __launch_bounds__(256) gemm_dual64(
    const float* __restrict__ in, int in_stride,
    const float* __restrict__ wl, const float* __restrict__ ws,
    const float* __restrict__ bl, const float* __restrict__ bs,
    const float* __restrict__ bias)
{
    const int K = 64;
    extern __shared__ float sm[];
    float* sh_wl = sm;                 // [K][64]
    float* sh_ws = sm + K * 64;        // [K][64]
    float* sh_h  = sm + 2 * K * 64;    // [64][K]

    const int tid = threadIdx.x;
    for (int i = tid; i < K * 16; i += 256) {
        ((float4*)sh_wl)[i] = ((const float4*)wl)[i];
        ((float4*)sh_ws)[i] = ((const float4*)ws)[i];
    }
    const int row0 = blockIdx.x * 64;
    for (int i = tid; i < 64 * (K / 4); i += 256) {
        int r = i / (K / 4), kq = i % (K / 4);
        int gr = row0 + r;
        float4 v = make_float4(0.f, 0.f, 0.f, 0.f);
        if (gr < NN) v = ((const float4*)(in + (size_t)gr * in_stride))[kq];
        ((float4*)(sh_h + r * K))[kq] = v;
    }
    __syncthreads();

    const int tx = tid & 15, ty = tid >> 4;
    const int c0 = tx * 4, r0 = ty * 4;

    float accl[4][4] = {}, accs[4][4] = {};
#pragma unroll 4
    for (int k0 = 0; k0 < K; k0 += 4) {
        float hh[4][4];
#pragma unroll
        for (int j = 0; j < 4; j++) {
            float4 hv = *(const float4*)(sh_h + (r0 + j) * K + k0);
            hh[j][0] = hv.x; hh[j][1] = hv.y; hh[j][2] = hv.z; hh[j][3] = hv.w;
        }
#pragma unroll
        for (int kk = 0; kk < 4; kk++) {
            const float4 wlv = ((const float4*)(sh_wl + (k0 + kk) * 64))[tx];
            const float4 wsv = ((const float4*)(sh_ws + (k0 + kk) * 64))[tx];
#pragma unroll
            for (int j = 0; j < 4; j++) {
                const float h = hh[j][kk];
                accl[j][0] += h * wlv.x; accl[j][1] += h * wlv.y;
                accl[j][2] += h * wlv.z; accl[j][3] += h * wlv.w;
                accs[j][0] += h * wsv.x; accs[j][1] += h * wsv.y;
                accs[j][2] += h * wsv.z; accs[j][3] += h * wsv.w;
            }
        }
    }

    float4 bt;
    bt.x = bl[c0+0] + bs[c0+0] + bias[c0+0];
    bt.y = bl[c0+1] + bs[c0+1] + bias[c0+1];
    bt.z = bl[c0+2] + bs[c0+2] + bias[c0+2];
    bt.w = bl[c0+3] + bs[c0+3] + bias[c0+3];

#pragma unroll
    for (int j = 0; j < 4; j++) {
        int gr = row0 + r0 + j;
        if (gr < NN) {
            __half2 p0 = __floats2half2_rn(accl[j][0], accl[j][1]);
            __half2 p1 = __floats2half2_rn(accl[j][2], accl[j][3]);
            uint2 u = make_uint2(*(unsigned*)&p0, *(unsigned*)&p1);
            ((uint2*)(g_ylin_h + gr * 64))[tx] = u;
            float4 hp = make_float4(accs[j][0] + bt.x, accs[j][1] + bt.y,
                                    accs[j][2] + bt.z, accs[j][3] + bt.w);
            ((float4*)(g_hpre + gr * 64))[tx] = hp;
        }
    }
}

// ============================================================================
// Gather (R10 loop, known good): pipelined index prefetch, fp32 accumulate.
// ============================================================================
__device__ __forceinline__ void acc8(float* acc, uint4 u)
{
    float2 f;
    f = __half22float2(*(__half2*)&u.x); acc[0] += f.x; acc[1] += f.y;
    f = __half22float2(*(__half2*)&u.y); acc[2] += f.x; acc[3] += f.y;
    f = __half22float2(*(__half2*)&u.z); acc[4] += f.x; acc[5] += f.y;
    f = __half22float2(*(__half2*)&u.w); acc[6] += f.x; acc[7] += f.y;
}

__device__ __forceinline__ void gather_node(int v, int q, float* acc)
{
    const int beg = g_rowptr[v];
    const int end = g_rowptr[v + 1];
    const uint4* base = (const uint4*)g_ylin_h;   // 8 uint4 per node row
    int e = beg;
    if (e + 4 <= end) {
        int i0 = g_csr_src[e + 0];
        int i1 = g_csr_src[e + 1];
        int i2 = g_csr_src[e + 2];
        int i3 = g_csr_src[e + 3];
        while (e + 8 <= end) {
            uint4 a = base[i0 * 8 + q];
            uint4 b = base[i1 * 8 + q];
            uint4 c = base[i2 * 8 + q];
            uint4 d = base[i3 * 8 + q];
            i0 = g_csr_src[e + 4];
            i1 = g_csr_src[e + 5];
            i2 = g_csr_src[e + 6];
            i3 = g_csr_src[e + 7];
            acc8(acc, a); acc8(acc, b); acc8(acc, c); acc8(acc, d);
            e += 4;
        }
        {
            uint4 a = base[i0 * 8 + q];
            uint4 b = base[i1 * 8 + q];
            uint4 c = base[i2 * 8 + q];
            uint4 d = base[i3 * 8 + q];
            acc8(acc, a); acc8(acc, b); acc8(acc, c); acc8(acc, d);
            e += 4;
        }
    }
    for (; e < end; e++) {
        int s = g_csr_src[e];
        acc8(acc, base[s * 8 + q]);
    }
}

__global__ void __launch_bounds__(256) gather_relu(int layer)
{
    const int t = blockIdx.x * 256 + threadIdx.x;
    const int v = t >> 3;
    const int q = t & 7;
    if (v >= NN) return;
    float acc[8] = {};
    gather_node(v, q, acc);
    const float4 hp0 = *(const float4*)(g_hpre + v * 64 + q * 8);
    const float4 hp1 = *(const float4*)(g_hpre + v * 64 + q * 8 + 4);
    float* outp = g_hcat + (size_t)v * HCATW + layer * UNITS + q * 8;
    float4 o0, o1;
    o0.x = fmaxf(hp0.x + acc[0], 0.f);
    o0.y = fmaxf(hp0.y + acc[1], 0.f);
    o0.z = fmaxf(hp0.z + acc[2], 0.f);
    o0.w = fmaxf(hp0.w + acc[3], 0.f);
    o1.x = fmaxf(hp1.x + acc[4], 0.f);
    o1.y = fmaxf(hp1.y + acc[5], 0.f);
    o1.z = fmaxf(hp1.z + acc[6], 0.f);
    o1.w = fmaxf(hp1.w + acc[7], 0.f);
    *(float4*)(outp)     = o0;
    *(float4*)(outp + 4) = o1;
}

// ============================================================================
// Final: out = hcat @ w_last + b_last   [NN,384] @ [384,40]
// Weights tiled per-kt ([64][40] slice, 10KB): smem 77.8KB -> 26.6KB,
// occupancy 2 -> 8 blocks/SM. fp32 math identical to R14 (same k order).
// ============================================================================
__global__ void __launch_bounds__(160) gemm_last(
    const float* __restrict__ w, const float* __restrict__ b,
    float* __restrict__ out)
{
    extern __shared__ float sm[];
    float* sh_w = sm;                  // [64][40] per-kt tile
    float* sh_h = sm + 64 * OUTF;      // [64][64]

    const int tid = threadIdx.x;       // 0..159
    const int row0 = blockIdx.x * 64;
    const int tx = tid % 10, ty = tid / 10;
    const int c0 = tx * 4, r0 = ty * 4;
    float acc[4][4] = {};

    for (int kt = 0; kt < HCATW / 64; kt++) {
        __syncthreads();
        // weight tile: 64*40 floats contiguous at w + kt*2560
        {
            const float4* wt = (const float4*)(w + kt * 2560);
            for (int i = tid; i < 640; i += 160) ((float4*)sh_w)[i] = wt[i];
        }
        // h tile: 64 rows x 64 fp32
        for (int i = tid; i < 64 * 16; i += 160) {
            int r = i / 16, kq = i % 16;
            int gr = row0 + r;
            float4 v = make_float4(0.f, 0.f, 0.f, 0.f);
            if (gr < NN) v = *(const float4*)(g_hcat + (size_t)gr * HCATW + kt * 64 + kq * 4);
            ((float4*)(sh_h + r * 64))[kq] = v;
        }
        __syncthreads();
#pragma unroll 4
        for (int k0 = 0; k0 < 64; k0 += 4) {
            float hh[4][4];
#pragma unroll
            for (int j = 0; j < 4; j++) {
                float4 hv = *(const float4*)(sh_h + (r0 + j) * 64 + k0);
                hh[j][0] = hv.x; hh[j][1] = hv.y; hh[j][2] = hv.z; hh[j][3] = hv.w;
            }
#pragma unroll
            for (int kk = 0; kk < 4; kk++) {
                const float4 wv = ((const float4*)(sh_w + (k0 + kk) * OUTF))[tx];
#pragma unroll
                for (int j = 0; j < 4; j++) {
                    const float h = hh[j][kk];
                    acc[j][0] += h * wv.x; acc[j][1] += h * wv.y;
                    acc[j][2] += h * wv.z; acc[j][3] += h * wv.w;
                }
            }
        }
    }

    float4 bv = *(const float4*)(b + c0);
#pragma unroll
    for (int j = 0; j < 4; j++) {
        int gr = row0 + r0 + j;
        if (gr < NN) {
            float4 o = make_float4(acc[j][0] + bv.x, acc[j][1] + bv.y,
                                   acc[j][2] + bv.z, acc[j][3] + bv.w);
            *(float4*)(out + (size_t)gr * OUTF + c0) = o;
        }
    }
}

// ============================================================================
extern "C" void kernel_launch(void* const* d_in, const int* in_sizes, int n_in,
                              void* d_out, int out_size)
{
    const float* x      = (const float*)d_in[0];
    const int*   src    = (const int*)  d_in[1];
    const int*   dst    = (const int*)  d_in[2];
    const float* w0l    = (const float*)d_in[3];
    const float* b0l    = (const float*)d_in[4];
    const float* w0s    = (const float*)d_in[5];
    const float* b0s    = (const float*)d_in[6];
    const float* bias0  = (const float*)d_in[7];
    const float* w_lin  = (const float*)d_in[8];
    const float* b_lin  = (const float*)d_in[9];
    const float* w_self = (const float*)d_in[10];
    const float* b_self = (const float*)d_in[11];
    const float* bias   = (const float*)d_in[12];
    const float* w_last = (const float*)d_in[13];
    const float* b_last = (const float*)d_in[14];
    float* out = (float*)d_out;

    const int SMEM0 = (3 * INF * 64) * 4;                       // 98304
    const int SMEM1 = (3 * 64 * 64) * 4;                        // 49152
    const int SMEML = (64 * OUTF + 64 * 64) * 4;                // 26624

    cudaFuncSetAttribute((const void*)hist_and_gemm0,
                         cudaFuncAttributeMaxDynamicSharedMemorySize, SMEM0);
    cudaFuncSetAttribute((const void*)gemm_dual64,
                         cudaFuncAttributeMaxDynamicSharedMemorySize, SMEM1);
    cudaFuncSetAttribute((const void*)gemm_last,
                         cudaFuncAttributeMaxDynamicSharedMemorySize, SMEML);

    void* hcat_p = nullptr;
    cudaGetSymbolAddress(&hcat_p, g_hcat);
    const float* hcat = (const float*)hcat_p;
    void* deg_p = nullptr;
    cudaGetSymbolAddress(&deg_p, g_deg);

    const int nblk     = (NN + 63) / 64;            // 782
    const int eblk     = (NE + 255) / 256;          // 6250
    const int gathblk  = (NN * 8 + 255) / 256;      // 1563

    // ---- CSR build overlapped with layer-0 GEMM ----
    cudaMemsetAsync(deg_p, 0, NN * sizeof(int));
    hist_and_gemm0<<<HIST_BLKS + GEMM_BLKS, 256, SMEM0>>>(
        dst, x, w0l, w0s, b0l, b0s, bias0);
    scan_csr<<<1, 1024>>>();
    fill_csr<<<eblk, 256>>>(src, dst);

    // ---- Layer 0 gather ----
    gather_relu<<<gathblk, 256>>>(0);

    // ---- Layers 1..5 ----
    for (int l = 1; l < NL; l++) {
        const float* in = hcat + (l - 1) * UNITS;
        const float* wl = w_lin  + (l - 1) * 64 * 64;
        const float* bl = b_lin  + (l - 1) * 64;
        const float* ws = w_self + (l - 1) * 64 * 64;
        const float* bs = b_self + (l - 1) * 64;
        const float* bi = bias   + (l - 1) * 64;
        gemm_dual64<<<nblk, 256, SMEM1>>>(in, HCATW, wl, ws, bl, bs, bi);
        gather_relu<<<gathblk, 256>>>(l);
    }

    // ---- Final projection ----
    gemm_last<<<nblk, 160, SMEML>>>(w_last, b_last, out);
}

// round 17
// speedup vs baseline: 1.2637x; 1.0935x over previous
#include <cuda_runtime.h>
#include <cuda_fp16.h>
#include <cuda_bf16.h>

#define NN 50000
#define NE 1600000
#define INF 128
#define UNITS 64
#define OUTF 40
#define NL 6
#define HCATW (NL * UNITS)   // 384
#define NB 196               // ceil(NN/256) scan blocks

// ---- device-global scratch (no allocation allowed) ----
__device__ __half g_ylin_h[NN * UNITS];     // h @ w_lin in fp16 (gather source)
__device__ float  g_hpre[NN * UNITS];       // h @ w_self + (bl+bs+bias), fp32
__device__ float  g_hcat[NN * HCATW];       // relu'd layer outputs, fp32 (fp16 overflows!)
__device__ int    g_deg[NN];
__device__ int    g_rowptr[NN + 1];
__device__ int    g_cursor[NN];
__device__ int    g_csr_src[NE];
__device__ int    g_bsum[NB];
__device__ int    g_boff[NB];

// ============================================================================
// CSR build: parallel 3-kernel scan (replaces single-block scan_csr)
// ============================================================================
__global__ void local_scan()          // NB blocks x 256
{
    __shared__ int sm[256];
    const int t = threadIdx.x;
    const int idx = blockIdx.x * 256 + t;
    const int d = (idx < NN) ? g_deg[idx] : 0;
    sm[t] = d;
    __syncthreads();
    for (int off = 1; off < 256; off <<= 1) {
        int v = (t >= off) ? sm[t - off] : 0;
        __syncthreads();
        sm[t] += v;
        __syncthreads();
    }
    if (idx < NN) g_rowptr[idx] = sm[t] - d;        // block-local exclusive
    if (t == 255) g_bsum[blockIdx.x] = sm[255];
}

__global__ void scan_bsums()          // 1 block x 256
{
    __shared__ int sm[256];
    const int t = threadIdx.x;
    const int v = (t < NB) ? g_bsum[t] : 0;
    sm[t] = v;
    __syncthreads();
    for (int off = 1; off < 256; off <<= 1) {
        int u = (t >= off) ? sm[t - off] : 0;
        __syncthreads();
        sm[t] += u;
        __syncthreads();
    }
    if (t < NB) g_boff[t] = sm[t] - v;              // exclusive
}

__global__ void add_off()             // NB blocks x 256
{
    const int idx = blockIdx.x * 256 + threadIdx.x;
    if (idx < NN) {
        int r = g_rowptr[idx] + g_boff[blockIdx.x];
        g_rowptr[idx] = r;
        g_cursor[idx] = r;
    }
    if (idx == 0) g_rowptr[NN] = NE;                // total degree == NE
}

__global__ void fill_csr(const int* __restrict__ src, const int* __restrict__ dst)
{
    int e = blockIdx.x * 256 + threadIdx.x;
    if (e >= NE) return;
    int pos = atomicAdd(&g_cursor[dst[e]], 1);
    g_csr_src[pos] = src[e];
}

// ============================================================================
// Merged kernel: blocks [0, HIST_BLKS) histogram; rest = layer-0 dual GEMM.
// ============================================================================
#define HIST_BLKS 1024
#define GEMM_BLKS ((NN + 63) / 64)   // 782

__global__ void hist_and_gemm0(const int* __restrict__ dst,
                               const float* __restrict__ in,
                               const float* __restrict__ wl, const float* __restrict__ ws,
                               const float* __restrict__ bl, const float* __restrict__ bs,
                               const float* __restrict__ bias)
{
    if (blockIdx.x < HIST_BLKS) {
        for (int e = blockIdx.x * 256 + threadIdx.x; e < NE; e += HIST_BLKS * 256)
            atomicAdd(&g_deg[dst[e]], 1);
        return;
    }

    const int K = INF;
    extern __shared__ float sm[];
    float* sh_wl = sm;                 // [K][64]
    float* sh_ws = sm + K * 64;        // [K][64]
    float* sh_h  = sm + 2 * K * 64;    // [64][K]

    const int tid = threadIdx.x;
    for (int i = tid; i < K * 16; i += 256) {
        ((float4*)sh_wl)[i] = ((const float4*)wl)[i];
        ((float4*)sh_ws)[i] = ((const float4*)ws)[i];
    }
    const int row0 = (blockIdx.x - HIST_BLKS) * 64;
    for (int i = tid; i < 64 * (K / 4); i += 256) {
        int r = i / (K / 4), kq = i % (K / 4);
        int gr = row0 + r;
        float4 v = make_float4(0.f, 0.f, 0.f, 0.f);
        if (gr < NN) v = ((const float4*)(in + (size_t)gr * K))[kq];
        ((float4*)(sh_h + r * K))[kq] = v;
    }
    __syncthreads();

    const int tx = tid & 15, ty = tid >> 4;
    const int c0 = tx * 4, r0 = ty * 4;

    float accl[4][4] = {}, accs[4][4] = {};
#pragma unroll 4
    for (int k0 = 0; k0 < K; k0 += 4) {
        float hh[4][4];
#pragma unroll
        for (int j = 0; j < 4; j++) {
            float4 hv = *(const float4*)(sh_h + (r0 + j) * K + k0);
            hh[j][0] = hv.x; hh[j][1] = hv.y; hh[j][2] = hv.z; hh[j][3] = hv.w;
        }
#pragma unroll
        for (int kk = 0; kk < 4; kk++) {
            const float4 wlv = ((const float4*)(sh_wl + (k0 + kk) * 64))[tx];
            const float4 wsv = ((const float4*)(sh_ws + (k0 + kk) * 64))[tx];
#pragma unroll
            for (int j = 0; j < 4; j++) {
                const float h = hh[j][kk];
                accl[j][0] += h * wlv.x; accl[j][1] += h * wlv.y;
                accl[j][2] += h * wlv.z; accl[j][3] += h * wlv.w;
                accs[j][0] += h * wsv.x; accs[j][1] += h * wsv.y;
                accs[j][2] += h * wsv.z; accs[j][3] += h * wsv.w;
            }
        }
    }

    float4 bt;
    bt.x = bl[c0+0] + bs[c0+0] + bias[c0+0];
    bt.y = bl[c0+1] + bs[c0+1] + bias[c0+1];
    bt.z = bl[c0+2] + bs[c0+2] + bias[c0+2];
    bt.w = bl[c0+3] + bs[c0+3] + bias[c0+3];

#pragma unroll
    for (int j = 0; j < 4; j++) {
        int gr = row0 + r0 + j;
        if (gr < NN) {
            __half2 p0 = __floats2half2_rn(accl[j][0], accl[j][1]);
            __half2 p1 = __floats2half2_rn(accl[j][2], accl[j][3]);
            uint2 u = make_uint2(*(unsigned*)&p0, *(unsigned*)&p1);
            ((uint2*)(g_ylin_h + gr * 64))[tx] = u;
            float4 hp = make_float4(accs[j][0] + bt.x, accs[j][1] + bt.y,
                                    accs[j][2] + bt.z, accs[j][3] + bt.w);
            ((float4*)(g_hpre + gr * 64))[tx] = hp;
        }
    }
}

// ============================================================================
// Inner-layer dual GEMM (K = 64): 8x4 register tile, 128 threads.
// Per 4-k batch: 8 h-LDS.128 + 8 w-LDS.128 feed 256 FFMAs.
// fp32 accumulation order per output element identical to R16.
// ============================================================================
__global__ void __launch_bounds__(128) gemm_dual64(
    const float* __restrict__ in, int in_stride,
    const float* __restrict__ wl, const float* __restrict__ ws,
    const float* __restrict__ bl, const float* __restrict__ bs,
    const float* __restrict__ bias)
{
    const int K = 64;
    extern __shared__ float sm[];
    float* sh_wl = sm;                 // [K][64]
    float* sh_ws = sm + K * 64;        // [K][64]
    float* sh_h  = sm + 2 * K * 64;    // [64][K]

    const int tid = threadIdx.x;       // 0..127
    for (int i = tid; i < K * 16; i += 128) {
        ((float4*)sh_wl)[i] = ((const float4*)wl)[i];
        ((float4*)sh_ws)[i] = ((const float4*)ws)[i];
    }
    const int row0 = blockIdx.x * 64;
    for (int i = tid; i < 64 * (K / 4); i += 128) {
        int r = i / (K / 4), kq = i % (K / 4);
        int gr = row0 + r;
        float4 v = make_float4(0.f, 0.f, 0.f, 0.f);
        if (gr < NN) v = ((const float4*)(in + (size_t)gr * in_stride))[kq];
        ((float4*)(sh_h + r * K))[kq] = v;
    }
    __syncthreads();

    const int tx = tid & 15, ry = tid >> 4;   // 16 col-groups x 8 row-groups
    const int c0 = tx * 4, r0 = ry * 8;

    float accl[8][4] = {}, accs[8][4] = {};
#pragma unroll 2
    for (int k0 = 0; k0 < K; k0 += 4) {
        float hh[8][4];
#pragma unroll
        for (int j = 0; j < 8; j++) {
            float4 hv = *(const float4*)(sh_h + (r0 + j) * K + k0);
            hh[j][0] = hv.x; hh[j][1] = hv.y; hh[j][2] = hv.z; hh[j][3] = hv.w;
        }
#pragma unroll
        for (int kk = 0; kk < 4; kk++) {
            const float4 wlv = ((const float4*)(sh_wl + (k0 + kk) * 64))[tx];
            const float4 wsv = ((const float4*)(sh_ws + (k0 + kk) * 64))[tx];
#pragma unroll
            for (int j = 0; j < 8; j++) {
                const float h = hh[j][kk];
                accl[j][0] += h * wlv.x; accl[j][1] += h * wlv.y;
                accl[j][2] += h * wlv.z; accl[j][3] += h * wlv.w;
                accs[j][0] += h * wsv.x; accs[j][1] += h * wsv.y;
                accs[j][2] += h * wsv.z; accs[j][3] += h * wsv.w;
            }
        }
    }

    float4 bt;
    bt.x = bl[c0+0] + bs[c0+0] + bias[c0+0];
    bt.y = bl[c0+1] + bs[c0+1] + bias[c0+1];
    bt.z = bl[c0+2] + bs[c0+2] + bias[c0+2];
    bt.w = bl[c0+3] + bs[c0+3] + bias[c0+3];

#pragma unroll
    for (int j = 0; j < 8; j++) {
        int gr = row0 + r0 + j;
        if (gr < NN) {
            __half2 p0 = __floats2half2_rn(accl[j][0], accl[j][1]);
            __half2 p1 = __floats2half2_rn(accl[j][2], accl[j][3]);
            uint2 u = make_uint2(*(unsigned*)&p0, *(unsigned*)&p1);
            ((uint2*)(g_ylin_h + gr * 64))[tx] = u;
            float4 hp = make_float4(accs[j][0] + bt.x, accs[j][1] + bt.y,
                                    accs[j][2] + bt.z, accs[j][3] + bt.w);
            ((float4*)(g_hpre + gr * 64))[tx] = hp;
        }
    }
}

// ============================================================================
// Gather (R10 loop, known good): pipelined index prefetch, fp32 accumulate.
// ============================================================================
__device__ __forceinline__ void acc8(float* acc, uint4 u)
{
    float2 f;
    f = __half22float2(*(__half2*)&u.x); acc[0] += f.x; acc[1] += f.y;
    f = __half22float2(*(__half2*)&u.y); acc[2] += f.x; acc[3] += f.y;
    f = __half22float2(*(__half2*)&u.z); acc[4] += f.x; acc[5] += f.y;
    f = __half22float2(*(__half2*)&u.w); acc[6] += f.x; acc[7] += f.y;
}

__device__ __forceinline__ void gather_node(int v, int q, float* acc)
{
    const int beg = g_rowptr[v];
    const int end = g_rowptr[v + 1];
    const uint4* base = (const uint4*)g_ylin_h;   // 8 uint4 per node row
    int e = beg;
    if (e + 4 <= end) {
        int i0 = g_csr_src[e + 0];
        int i1 = g_csr_src[e + 1];
        int i2 = g_csr_src[e + 2];
        int i3 = g_csr_src[e + 3];
        while (e + 8 <= end) {
            uint4 a = base[i0 * 8 + q];
            uint4 b = base[i1 * 8 + q];
            uint4 c = base[i2 * 8 + q];
            uint4 d = base[i3 * 8 + q];
            i0 = g_csr_src[e + 4];
            i1 = g_csr_src[e + 5];
            i2 = g_csr_src[e + 6];
            i3 = g_csr_src[e + 7];
            acc8(acc, a); acc8(acc, b); acc8(acc, c); acc8(acc, d);
            e += 4;
        }
        {
            uint4 a = base[i0 * 8 + q];
            uint4 b = base[i1 * 8 + q];
            uint4 c = base[i2 * 8 + q];
            uint4 d = base[i3 * 8 + q];
            acc8(acc, a); acc8(acc, b); acc8(acc, c); acc8(acc, d);
            e += 4;
        }
    }
    for (; e < end; e++) {
        int s = g_csr_src[e];
        acc8(acc, base[s * 8 + q]);
    }
}

__global__ void __launch_bounds__(256) gather_relu(int layer)
{
    const int t = blockIdx.x * 256 + threadIdx.x;
    const int v = t >> 3;
    const int q = t & 7;
    if (v >= NN) return;
    float acc[8] = {};
    gather_node(v, q, acc);
    const float4 hp0 = *(const float4*)(g_hpre + v * 64 + q * 8);
    const float4 hp1 = *(const float4*)(g_hpre + v * 64 + q * 8 + 4);
    float* outp = g_hcat + (size_t)v * HCATW + layer * UNITS + q * 8;
    float4 o0, o1;
    o0.x = fmaxf(hp0.x + acc[0], 0.f);
    o0.y = fmaxf(hp0.y + acc[1], 0.f);
    o0.z = fmaxf(hp0.z + acc[2], 0.f);
    o0.w = fmaxf(hp0.w + acc[3], 0.f);
    o1.x = fmaxf(hp1.x + acc[4], 0.f);
    o1.y = fmaxf(hp1.y + acc[5], 0.f);
    o1.z = fmaxf(hp1.z + acc[6], 0.f);
    o1.w = fmaxf(hp1.w + acc[7], 0.f);
    *(float4*)(outp)     = o0;
    *(float4*)(outp + 4) = o1;
}

// ============================================================================
// Final: out = hcat @ w_last + b_last   [NN,384] @ [384,40]
// Per-kt weight tiles (R16, known good: 26.6KB smem, 8 blocks/SM).
// ============================================================================
__global__ void __launch_bounds__(160) gemm_last(
    const float* __restrict__ w, const float* __restrict__ b,
    float* __restrict__ out)
{
    extern __shared__ float sm[];
    float* sh_w = sm;                  // [64][40] per-kt tile
    float* sh_h = sm + 64 * OUTF;      // [64][64]

    const int tid = threadIdx.x;       // 0..159
    const int row0 = blockIdx.x * 64;
    const int tx = tid % 10, ty = tid / 10;
    const int c0 = tx * 4, r0 = ty * 4;
    float acc[4][4] = {};

    for (int kt = 0; kt < HCATW / 64; kt++) {
        __syncthreads();
        {
            const float4* wt = (const float4*)(w + kt * 2560);
            for (int i = tid; i < 640; i += 160) ((float4*)sh_w)[i] = wt[i];
        }
        for (int i = tid; i < 64 * 16; i += 160) {
            int r = i / 16, kq = i % 16;
            int gr = row0 + r;
            float4 v = make_float4(0.f, 0.f, 0.f, 0.f);
            if (gr < NN) v = *(const float4*)(g_hcat + (size_t)gr * HCATW + kt * 64 + kq * 4);
            ((float4*)(sh_h + r * 64))[kq] = v;
        }
        __syncthreads();
#pragma unroll 4
        for (int k0 = 0; k0 < 64; k0 += 4) {
            float hh[4][4];
#pragma unroll
            for (int j = 0; j < 4; j++) {
                float4 hv = *(const float4*)(sh_h + (r0 + j) * 64 + k0);
                hh[j][0] = hv.x; hh[j][1] = hv.y; hh[j][2] = hv.z; hh[j][3] = hv.w;
            }
#pragma unroll
            for (int kk = 0; kk < 4; kk++) {
                const float4 wv = ((const float4*)(sh_w + (k0 + kk) * OUTF))[tx];
#pragma unroll
                for (int j = 0; j < 4; j++) {
                    const float h = hh[j][kk];
                    acc[j][0] += h * wv.x; acc[j][1] += h * wv.y;
                    acc[j][2] += h * wv.z; acc[j][3] += h * wv.w;
                }
            }
        }
    }

    float4 bv = *(const float4*)(b + c0);
#pragma unroll
    for (int j = 0; j < 4; j++) {
        int gr = row0 + r0 + j;
        if (gr < NN) {
            float4 o = make_float4(acc[j][0] + bv.x, acc[j][1] + bv.y,
                                   acc[j][2] + bv.z, acc[j][3] + bv.w);
            *(float4*)(out + (size_t)gr * OUTF + c0) = o;
        }
    }
}

// ============================================================================
extern "C" void kernel_launch(void* const* d_in, const int* in_sizes, int n_in,
                              void* d_out, int out_size)
{
    const float* x      = (const float*)d_in[0];
    const int*   src    = (const int*)  d_in[1];
    const int*   dst    = (const int*)  d_in[2];
    const float* w0l    = (const float*)d_in[3];
    const float* b0l    = (const float*)d_in[4];
    const float* w0s    = (const float*)d_in[5];
    const float* b0s    = (const float*)d_in[6];
    const float* bias0  = (const float*)d_in[7];
    const float* w_lin  = (const float*)d_in[8];
    const float* b_lin  = (const float*)d_in[9];
    const float* w_self = (const float*)d_in[10];
    const float* b_self = (const float*)d_in[11];
    const float* bias   = (const float*)d_in[12];
    const float* w_last = (const float*)d_in[13];
    const float* b_last = (const float*)d_in[14];
    float* out = (float*)d_out;

    const int SMEM0 = (3 * INF * 64) * 4;                       // 98304
    const int SMEM1 = (3 * 64 * 64) * 4;                        // 49152
    const int SMEML = (64 * OUTF + 64 * 64) * 4;                // 26624

    cudaFuncSetAttribute((const void*)hist_and_gemm0,
                         cudaFuncAttributeMaxDynamicSharedMemorySize, SMEM0);
    cudaFuncSetAttribute((const void*)gemm_dual64,
                         cudaFuncAttributeMaxDynamicSharedMemorySize, SMEM1);
    cudaFuncSetAttribute((const void*)gemm_last,
                         cudaFuncAttributeMaxDynamicSharedMemorySize, SMEML);

    void* hcat_p = nullptr;
    cudaGetSymbolAddress(&hcat_p, g_hcat);
    const float* hcat = (const float*)hcat_p;
    void* deg_p = nullptr;
    cudaGetSymbolAddress(&deg_p, g_deg);

    const int nblk     = (NN + 63) / 64;            // 782
    const int eblk     = (NE + 255) / 256;          // 6250
    const int gathblk  = (NN * 8 + 255) / 256;      // 1563

    // ---- CSR build overlapped with layer-0 GEMM ----
    cudaMemsetAsync(deg_p, 0, NN * sizeof(int));
    hist_and_gemm0<<<HIST_BLKS + GEMM_BLKS, 256, SMEM0>>>(
        dst, x, w0l, w0s, b0l, b0s, bias0);
    local_scan<<<NB, 256>>>();
    scan_bsums<<<1, 256>>>();
    add_off<<<NB, 256>>>();
    fill_csr<<<eblk, 256>>>(src, dst);

    // ---- Layer 0 gather ----
    gather_relu<<<gathblk, 256>>>(0);

    // ---- Layers 1..5 ----
    for (int l = 1; l < NL; l++) {
        const float* in = hcat + (l - 1) * UNITS;
        const float* wl = w_lin  + (l - 1) * 64 * 64;
        const float* bl = b_lin  + (l - 1) * 64;
        const float* ws = w_self + (l - 1) * 64 * 64;
        const float* bs = b_self + (l - 1) * 64;
        const float* bi = bias   + (l - 1) * 64;
        gemm_dual64<<<nblk, 128, SMEM1>>>(in, HCATW, wl, ws, bl, bs, bi);
        gather_relu<<<gathblk, 256>>>(l);
    }

    // ---- Final projection ----
    gemm_last<<<nblk, 160, SMEML>>>(w_last, b_last, out);
}